// round 10
// baseline (speedup 1.0000x reference)
#include <cuda_runtime.h>
#include <math.h>

#define BSZ   4
#define NTOK  1024
#define DIN   384
#define SST   16
#define NROWS 4096
#define NCOLS 816
#define COLS_PAD 832

__device__ __align__(16) float g_wpack[DIN * COLS_PAD];
__device__ __align__(16) float g_bias[COLS_PAD];
__device__ __align__(16) float g_xT[DIN * NROWS];
__device__ __align__(16) float g_scratch[COLS_PAD * NROWS];

__device__ __forceinline__ float softplusf(float z) {
    return (z > 20.f) ? z : log1pf(expf(z));
}

// ---------------- packed f32x2 helpers ----------------
typedef unsigned long long f2;
__device__ __forceinline__ f2 pk(float lo, float hi) {
    f2 r; asm("mov.b64 %0,{%1,%2};" : "=l"(r) : "f"(lo), "f"(hi)); return r;
}
__device__ __forceinline__ void up2(f2 v, float& lo, float& hi) {
    asm("mov.b64 {%0,%1},%2;" : "=f"(lo), "=f"(hi) : "l"(v));
}
__device__ __forceinline__ f2 fma2(f2 a, f2 b, f2 c) {
    f2 r; asm("fma.rn.f32x2 %0,%1,%2,%3;" : "=l"(r) : "l"(a), "l"(b), "l"(c)); return r;
}
__device__ __forceinline__ f2 mul2(f2 a, f2 b) {
    f2 r; asm("mul.rn.f32x2 %0,%1,%2;" : "=l"(r) : "l"(a), "l"(b)); return r;
}

// ---------------- kernel 0a: pack weights k-major + bias ----------------
__global__ void pack_kernel(const float* __restrict__ dtsW, const float* __restrict__ dtsb,
                            const float* __restrict__ dtdW, const float* __restrict__ dtdb,
                            const float* __restrict__ BW,   const float* __restrict__ CrW,
                            const float* __restrict__ CiW) {
    int i = blockIdx.x * blockDim.x + threadIdx.x;
    if (i >= DIN * COLS_PAD) return;
    int k = i / COLS_PAD;
    int c = i % COLS_PAD;
    float v = 0.f;
    if      (c < 384) v = dtsW[c * DIN + k];
    else if (c < 768) v = dtdW[(c - 384) * DIN + k];
    else if (c < 784) v = BW [k * SST + (c - 768)];
    else if (c < 800) v = CrW[k * SST + (c - 784)];
    else if (c < 816) v = CiW[k * SST + (c - 800)];
    g_wpack[i] = v;
    if (k == 0) {
        float bv = 0.f;
        if (c < 384)      bv = dtsb[c];
        else if (c < 768) bv = dtdb[c - 384];
        g_bias[c] = bv;
    }
}

// ---------------- kernel 0b: transpose x -> xT[d][row] ----------------
__global__ void transpose_x(const float* __restrict__ x) {
    __shared__ float tile[32][33];
    int kb = blockIdx.x * 32;
    int rb = blockIdx.y * 32;
    int tx = threadIdx.x, ty = threadIdx.y;
    #pragma unroll
    for (int i = ty; i < 32; i += 8)
        tile[i][tx] = x[(rb + i) * DIN + kb + tx];
    __syncthreads();
    #pragma unroll
    for (int i = ty; i < 32; i += 8)
        g_xT[(kb + i) * NROWS + rb + tx] = tile[tx][i];
}

// ---------------- kernel 1: GEMM, 8x8 per thread ----------------
#define GBM 64
#define GBN 128
#define GBK 16
__global__ __launch_bounds__(128) void gemm_kernel() {
    __shared__ float Ws[GBK][68];
    __shared__ float Xs[GBK][GBN + 4];
    int tid = threadIdx.x;
    int tx = tid & 15;
    int ty = tid >> 4;
    int cBase = blockIdx.x * GBM;
    int rBase = blockIdx.y * GBN;

    f2 acc2[8][4];
    #pragma unroll
    for (int i = 0; i < 8; i++)
        #pragma unroll
        for (int j = 0; j < 4; j++) acc2[i][j] = pk(0.f, 0.f);

    for (int kB = 0; kB < DIN; kB += GBK) {
        #pragma unroll
        for (int ch = 0; ch < 2; ch++) {
            int idx = tid + ch * 128;
            int kk = idx >> 4, cc = (idx & 15) * 4;
            *(float4*)&Ws[kk][cc] = *(const float4*)&g_wpack[(kB + kk) * COLS_PAD + cBase + cc];
        }
        #pragma unroll
        for (int ch = 0; ch < 4; ch++) {
            int idx = tid + ch * 128;
            int kk = idx >> 5, rr = (idx & 31) * 4;
            *(float4*)&Xs[kk][rr] = *(const float4*)&g_xT[(kB + kk) * NROWS + rBase + rr];
        }
        __syncthreads();
        #pragma unroll
        for (int kk = 0; kk < GBK; kk++) {
            float a[8];
            *(float4*)&a[0] = *(const float4*)&Ws[kk][ty * 8];
            *(float4*)&a[4] = *(const float4*)&Ws[kk][ty * 8 + 4];
            float4 x0 = *(const float4*)&Xs[kk][tx * 4];
            float4 x1 = *(const float4*)&Xs[kk][64 + tx * 4];
            f2 b2[4] = { pk(x0.x, x0.y), pk(x0.z, x0.w), pk(x1.x, x1.y), pk(x1.z, x1.w) };
            #pragma unroll
            for (int i = 0; i < 8; i++) {
                f2 a2 = pk(a[i], a[i]);
                #pragma unroll
                for (int j = 0; j < 4; j++)
                    acc2[i][j] = fma2(a2, b2[j], acc2[i][j]);
            }
        }
        __syncthreads();
    }

    #pragma unroll
    for (int i = 0; i < 8; i++) {
        int c = cBase + ty * 8 + i;
        float bv = g_bias[c];
        bool act = (c < 768);
        float o[8];
        #pragma unroll
        for (int j = 0; j < 4; j++) up2(acc2[i][j], o[2 * j], o[2 * j + 1]);
        #pragma unroll
        for (int j = 0; j < 8; j++) {
            float v = o[j];
            if (act) v = fminf(softplusf(v + bv), 0.15f);
            o[j] = v;
        }
        *(float4*)&g_scratch[c * NROWS + rBase + tx * 4]      = *(float4*)&o[0];
        *(float4*)&g_scratch[c * NROWS + rBase + 64 + tx * 4] = *(float4*)&o[4];
    }
}

// ---------------- kernel 2: SSM — step0 exploits h_imag==0 (scalar real-only stencil) ----------------
#define SHS 36
__global__ __launch_bounds__(128, 4) void ssm_kernel(const float* __restrict__ conv_w,
                                                     const float* __restrict__ ralpha,
                                                     const float* __restrict__ rbeta,
                                                     const float* __restrict__ Dparam,
                                                     const float* __restrict__ A_log,
                                                     float* __restrict__ y) {
    __shared__ float shR0[32][SHS];   // step-0 real plane
    __shared__ float shR1[32][SHS];   // step-1 real plane
    __shared__ float shI1[32][SHS];   // step-1 imag plane

    int d   = blockIdx.x;
    int b   = blockIdx.y;
    int t   = threadIdx.x;
    int R0  = (t >> 3) * 2;
    int lane8 = t & 7;
    int pcb = lane8 * 4;
    int row0 = b * NTOK;
    int n0 = R0 * 32 + pcb;
    int n1 = n0 + 32;

    int rm = (R0 > 0)      ? R0 - 1 : 0;
    int rp = (R0 + 2 < 32) ? R0 + 2 : 31;

    float w[9];
    f2 w2[9];
    #pragma unroll
    for (int i = 0; i < 9; i++) {
        float wv = conv_w[d * 9 + i];
        w[i] = wv; w2[i] = pk(wv, wv);
    }
    float alpha = ralpha[d];
    float beta  = rbeta[d];
    float Dp    = Dparam[d];
    const f2 HALF2 = pk(0.5f, 0.5f);

    float xv[8], yacc[8], ds[8], dd[8];
    {
        float4 a = *(const float4*)&g_xT[d * NROWS + row0 + n0];
        float4 c = *(const float4*)&g_xT[d * NROWS + row0 + n1];
        xv[0]=a.x; xv[1]=a.y; xv[2]=a.z; xv[3]=a.w;
        xv[4]=c.x; xv[5]=c.y; xv[6]=c.z; xv[7]=c.w;
        a = *(const float4*)&g_scratch[d * NROWS + row0 + n0];
        c = *(const float4*)&g_scratch[d * NROWS + row0 + n1];
        ds[0]=a.x; ds[1]=a.y; ds[2]=a.z; ds[3]=a.w;
        ds[4]=c.x; ds[5]=c.y; ds[6]=c.z; ds[7]=c.w;
        a = *(const float4*)&g_scratch[(384 + d) * NROWS + row0 + n0];
        c = *(const float4*)&g_scratch[(384 + d) * NROWS + row0 + n1];
        dd[0]=a.x; dd[1]=a.y; dd[2]=a.z; dd[3]=a.w;
        dd[4]=c.x; dd[5]=c.y; dd[6]=c.z; dd[7]=c.w;
    }
    #pragma unroll
    for (int j = 0; j < 8; j++) yacc[j] = xv[j] * Dp;

    for (int s = 0; s < SST; s++) {
        float A = -softplusf(A_log[d * SST + s]);
        f2 A2 = pk(A, A);
        float ur[8];
        {
            float4 a = *(const float4*)&g_scratch[(768 + s) * NROWS + row0 + n0];
            float4 c = *(const float4*)&g_scratch[(768 + s) * NROWS + row0 + n1];
            ur[0]=xv[0]*a.x; ur[1]=xv[1]*a.y; ur[2]=xv[2]*a.z; ur[3]=xv[3]*a.w;
            ur[4]=xv[4]*c.x; ur[5]=xv[5]*c.y; ur[6]=xv[6]*c.z; ur[7]=xv[7]*c.w;
        }

        // ---------- step 0: h_imag == 0 -> scalar real-only stencil ----------
        *(float4*)&shR0[R0][pcb]   = make_float4(ur[0], ur[1], ur[2], ur[3]);
        *(float4*)&shR0[R0+1][pcb] = make_float4(ur[4], ur[5], ur[6], ur[7]);
        __syncthreads();

        int cl = (pcb > 0)  ? pcb - 1 : 0;
        int cr = (pcb < 28) ? pcb + 4 : 31;
        float4 tR4 = *(const float4*)&shR0[rm][pcb];
        float  tRl = shR0[rm][cl], tRr = shR0[rm][cr];
        float4 bR4 = *(const float4*)&shR0[rp][pcb];
        float  bRl = shR0[rp][cl], bRr = shR0[rp][cr];
        float e0l = __shfl_up_sync(0xffffffffu,   ur[3], 1);
        float e0r = __shfl_down_sync(0xffffffffu, ur[0], 1);
        float e1l = __shfl_up_sync(0xffffffffu,   ur[7], 1);
        float e1r = __shfl_down_sync(0xffffffffu, ur[4], 1);
        if (lane8 == 0) { e0l = ur[0]; e1l = ur[4]; }
        if (lane8 == 7) { e0r = ur[3]; e1r = ur[7]; }

        float T0[6] = {tRl, tR4.x, tR4.y, tR4.z, tR4.w, tRr};
        float M0s[6] = {e0l, ur[0], ur[1], ur[2], ur[3], e0r};
        float M1s[6] = {e1l, ur[4], ur[5], ur[6], ur[7], e1r};
        float B0[6] = {bRl, bR4.x, bR4.y, bR4.z, bR4.w, bRr};

        f2 hc[8];
        #pragma unroll
        for (int c = 0; c < 4; c++) {
            // row 0 pixel
            float lap =       w[0] * T0[c];
            lap = fmaf(w[1], T0[c+1], lap);
            lap = fmaf(w[2], T0[c+2], lap);
            lap = fmaf(w[3], M0s[c],   lap);
            lap = fmaf(w[4], M0s[c+1], lap);
            lap = fmaf(w[5], M0s[c+2], lap);
            lap = fmaf(w[6], M1s[c],   lap);
            lap = fmaf(w[7], M1s[c+1], lap);
            lap = fmaf(w[8], M1s[c+2], lap);
            {
                int j = c;
                float rs = fmaf(-beta * ur[j], ur[j], alpha);
                float f1r = ds[j] * fmaf(A, ur[j], ur[j]);
                float sumr = fmaf(ur[j], rs, f1r);
                float hr1 = fmaf(0.5f, sumr, ur[j]);
                float hi1 = 0.5f * dd[j] * lap;
                hc[j] = pk(hr1, hi1);
            }
            // row 1 pixel
            float lap2 =       w[0] * M0s[c];
            lap2 = fmaf(w[1], M0s[c+1], lap2);
            lap2 = fmaf(w[2], M0s[c+2], lap2);
            lap2 = fmaf(w[3], M1s[c],   lap2);
            lap2 = fmaf(w[4], M1s[c+1], lap2);
            lap2 = fmaf(w[5], M1s[c+2], lap2);
            lap2 = fmaf(w[6], B0[c],   lap2);
            lap2 = fmaf(w[7], B0[c+1], lap2);
            lap2 = fmaf(w[8], B0[c+2], lap2);
            {
                int j = 4 + c;
                float rs = fmaf(-beta * ur[j], ur[j], alpha);
                float f1r = ds[j] * fmaf(A, ur[j], ur[j]);
                float sumr = fmaf(ur[j], rs, f1r);
                float hr1 = fmaf(0.5f, sumr, ur[j]);
                float hi1 = 0.5f * dd[j] * lap2;
                hc[j] = pk(hr1, hi1);
            }
        }

        // ---------- step 1: full complex step (packed) ----------
        {
            float a0,b0,a1,b1,a2,b2,a3,b3;
            up2(hc[0],a0,b0); up2(hc[1],a1,b1); up2(hc[2],a2,b2); up2(hc[3],a3,b3);
            *(float4*)&shR1[R0][pcb] = make_float4(a0,a1,a2,a3);
            *(float4*)&shI1[R0][pcb] = make_float4(b0,b1,b2,b3);
            up2(hc[4],a0,b0); up2(hc[5],a1,b1); up2(hc[6],a2,b2); up2(hc[7],a3,b3);
            *(float4*)&shR1[R0+1][pcb] = make_float4(a0,a1,a2,a3);
            *(float4*)&shI1[R0+1][pcb] = make_float4(b0,b1,b2,b3);
        }
        __syncthreads();

        {
            float4 tR = *(const float4*)&shR1[rm][pcb];
            float4 tI = *(const float4*)&shI1[rm][pcb];
            float  tRl1 = shR1[rm][cl], tIl1 = shI1[rm][cl];
            float  tRr1 = shR1[rm][cr], tIr1 = shI1[rm][cr];
            float4 bR = *(const float4*)&shR1[rp][pcb];
            float4 bI = *(const float4*)&shI1[rp][pcb];
            float  bRl1 = shR1[rp][cl], bIl1 = shI1[rp][cl];
            float  bRr1 = shR1[rp][cr], bIr1 = shI1[rp][cr];

            float h0r,h0i,h3r,h3i,h4r,h4i,h7r,h7i;
            up2(hc[0],h0r,h0i); up2(hc[3],h3r,h3i);
            up2(hc[4],h4r,h4i); up2(hc[7],h7r,h7i);
            float e0lr = __shfl_up_sync(0xffffffffu,   h3r, 1);
            float e0li = __shfl_up_sync(0xffffffffu,   h3i, 1);
            float e0rr = __shfl_down_sync(0xffffffffu, h0r, 1);
            float e0ri = __shfl_down_sync(0xffffffffu, h0i, 1);
            float e1lr = __shfl_up_sync(0xffffffffu,   h7r, 1);
            float e1li = __shfl_up_sync(0xffffffffu,   h7i, 1);
            float e1rr = __shfl_down_sync(0xffffffffu, h4r, 1);
            float e1ri = __shfl_down_sync(0xffffffffu, h4i, 1);
            if (lane8 == 0) { e0lr=h0r; e0li=h0i; e1lr=h4r; e1li=h4i; }
            if (lane8 == 7) { e0rr=h3r; e0ri=h3i; e1rr=h7r; e1ri=h7i; }

            f2 T[6]  = { pk(tRl1,tIl1), pk(tR.x,tI.x), pk(tR.y,tI.y),
                         pk(tR.z,tI.z), pk(tR.w,tI.w), pk(tRr1,tIr1) };
            f2 Bw[6] = { pk(bRl1,bIl1), pk(bR.x,bI.x), pk(bR.y,bI.y),
                         pk(bR.z,bI.z), pk(bR.w,bI.w), pk(bRr1,bIr1) };
            f2 M0[6] = { pk(e0lr,e0li), hc[0], hc[1], hc[2], hc[3], pk(e0rr,e0ri) };
            f2 M1[6] = { pk(e1lr,e1li), hc[4], hc[5], hc[6], hc[7], pk(e1rr,e1ri) };

            f2 hn[8];
            #pragma unroll
            for (int c = 0; c < 4; c++) {
                f2 lap = mul2(w2[0], T[c]);
                lap = fma2(w2[1], T[c+1], lap);
                lap = fma2(w2[2], T[c+2], lap);
                lap = fma2(w2[3], M0[c],   lap);
                lap = fma2(w2[4], M0[c+1], lap);
                lap = fma2(w2[5], M0[c+2], lap);
                lap = fma2(w2[6], M1[c],   lap);
                lap = fma2(w2[7], M1[c+1], lap);
                lap = fma2(w2[8], M1[c+2], lap);
                {
                    int j = c;
                    float hrj, hij; up2(hc[j], hrj, hij);
                    float h2 = fmaf(hrj, hrj, hij * hij);
                    float rs = fmaf(-beta, h2, alpha);
                    f2 f1 = mul2(pk(ds[j], ds[j]), fma2(A2, hc[j], pk(ur[j], 0.f)));
                    float lr, li; up2(lap, lr, li);
                    f2 sum = fma2(pk(dd[j], dd[j]), pk(-li, lr), f1);
                    sum = fma2(hc[j], pk(rs, rs), sum);
                    hn[j] = fma2(HALF2, sum, hc[j]);
                }
                f2 lap2 = mul2(w2[0], M0[c]);
                lap2 = fma2(w2[1], M0[c+1], lap2);
                lap2 = fma2(w2[2], M0[c+2], lap2);
                lap2 = fma2(w2[3], M1[c],   lap2);
                lap2 = fma2(w2[4], M1[c+1], lap2);
                lap2 = fma2(w2[5], M1[c+2], lap2);
                lap2 = fma2(w2[6], Bw[c],   lap2);
                lap2 = fma2(w2[7], Bw[c+1], lap2);
                lap2 = fma2(w2[8], Bw[c+2], lap2);
                {
                    int j = 4 + c;
                    float hrj, hij; up2(hc[j], hrj, hij);
                    float h2 = fmaf(hrj, hrj, hij * hij);
                    float rs = fmaf(-beta, h2, alpha);
                    f2 f1 = mul2(pk(ds[j], ds[j]), fma2(A2, hc[j], pk(ur[j], 0.f)));
                    float lr, li; up2(lap2, lr, li);
                    f2 sum = fma2(pk(dd[j], dd[j]), pk(-li, lr), f1);
                    sum = fma2(hc[j], pk(rs, rs), sum);
                    hn[j] = fma2(HALF2, sum, hc[j]);
                }
            }
            #pragma unroll
            for (int j = 0; j < 8; j++) hc[j] = hn[j];
        }

        // output projection accumulate
        {
            float4 c0 = *(const float4*)&g_scratch[(784 + s) * NROWS + row0 + n0];
            float4 c1 = *(const float4*)&g_scratch[(784 + s) * NROWS + row0 + n1];
            float4 i0 = *(const float4*)&g_scratch[(800 + s) * NROWS + row0 + n0];
            float4 i1 = *(const float4*)&g_scratch[(800 + s) * NROWS + row0 + n1];
            float hr, hi;
            up2(hc[0], hr, hi); yacc[0] = fmaf(hr, c0.x, fmaf(hi, i0.x, yacc[0]));
            up2(hc[1], hr, hi); yacc[1] = fmaf(hr, c0.y, fmaf(hi, i0.y, yacc[1]));
            up2(hc[2], hr, hi); yacc[2] = fmaf(hr, c0.z, fmaf(hi, i0.z, yacc[2]));
            up2(hc[3], hr, hi); yacc[3] = fmaf(hr, c0.w, fmaf(hi, i0.w, yacc[3]));
            up2(hc[4], hr, hi); yacc[4] = fmaf(hr, c1.x, fmaf(hi, i1.x, yacc[4]));
            up2(hc[5], hr, hi); yacc[5] = fmaf(hr, c1.y, fmaf(hi, i1.y, yacc[5]));
            up2(hc[6], hr, hi); yacc[6] = fmaf(hr, c1.z, fmaf(hi, i1.z, yacc[6]));
            up2(hc[7], hr, hi); yacc[7] = fmaf(hr, c1.w, fmaf(hi, i1.w, yacc[7]));
        }
    }

    #pragma unroll
    for (int j = 0; j < 4; j++) {
        y[(row0 + n0 + j) * DIN + d] = yacc[j];
        y[(row0 + n1 + j) * DIN + d] = yacc[4 + j];
    }
}

// ---------------- launch ----------------
extern "C" void kernel_launch(void* const* d_in, const int* in_sizes, int n_in,
                              void* d_out, int out_size) {
    const float* x      = (const float*)d_in[0];
    const float* dtsW   = (const float*)d_in[1];
    const float* dtsb   = (const float*)d_in[2];
    const float* dtdW   = (const float*)d_in[3];
    const float* dtdb   = (const float*)d_in[4];
    const float* BW     = (const float*)d_in[5];
    const float* CrW    = (const float*)d_in[6];
    const float* CiW    = (const float*)d_in[7];
    const float* Dparam = (const float*)d_in[8];
    const float* A_log  = (const float*)d_in[9];
    const float* conv_w = (const float*)d_in[10];
    const float* ralpha = (const float*)d_in[11];
    const float* rbeta  = (const float*)d_in[12];
    float* y = (float*)d_out;

    pack_kernel<<<(DIN * COLS_PAD + 255) / 256, 256>>>(dtsW, dtsb, dtdW, dtdb, BW, CrW, CiW);
    transpose_x<<<dim3(DIN / 32, NROWS / 32), dim3(32, 8)>>>(x);
    gemm_kernel<<<dim3(COLS_PAD / GBM, NROWS / GBN), 128>>>();
    ssm_kernel<<<dim3(DIN, BSZ), 128>>>(conv_w, ralpha, rbeta, Dparam, A_log, y);
}

// round 11
// speedup vs baseline: 1.0827x; 1.0827x over previous
#include <cuda_runtime.h>
#include <math.h>

#define BSZ   4
#define NTOK  1024
#define DIN   384
#define SST   16
#define NROWS 4096
#define NCOLS 816
#define COLS_PAD 832

__device__ __align__(16) float g_wpack[DIN * COLS_PAD];
__device__ __align__(16) float g_bias[COLS_PAD];
__device__ __align__(16) float g_xT[DIN * NROWS];
__device__ __align__(16) float g_scratch[COLS_PAD * NROWS];

__device__ __forceinline__ float softplusf(float z) {
    return (z > 20.f) ? z : log1pf(expf(z));
}

// ---------------- packed f32x2 helpers ----------------
typedef unsigned long long f2;
__device__ __forceinline__ f2 pk(float lo, float hi) {
    f2 r; asm("mov.b64 %0,{%1,%2};" : "=l"(r) : "f"(lo), "f"(hi)); return r;
}
__device__ __forceinline__ void up2(f2 v, float& lo, float& hi) {
    asm("mov.b64 {%0,%1},%2;" : "=f"(lo), "=f"(hi) : "l"(v));
}
__device__ __forceinline__ f2 fma2(f2 a, f2 b, f2 c) {
    f2 r; asm("fma.rn.f32x2 %0,%1,%2,%3;" : "=l"(r) : "l"(a), "l"(b), "l"(c)); return r;
}
__device__ __forceinline__ f2 mul2(f2 a, f2 b) {
    f2 r; asm("mul.rn.f32x2 %0,%1,%2;" : "=l"(r) : "l"(a), "l"(b)); return r;
}

// ---------------- cp.async helpers ----------------
__device__ __forceinline__ void cpa16(void* smem_ptr, const void* gmem_ptr) {
    unsigned sa = (unsigned)__cvta_generic_to_shared(smem_ptr);
    asm volatile("cp.async.ca.shared.global [%0], [%1], 16;" :: "r"(sa), "l"(gmem_ptr));
}
__device__ __forceinline__ void cpa_commit() { asm volatile("cp.async.commit_group;"); }
__device__ __forceinline__ void cpa_wait0()  { asm volatile("cp.async.wait_group 0;"); }

// ---------------- kernel 0a: pack weights k-major + bias ----------------
__global__ void pack_kernel(const float* __restrict__ dtsW, const float* __restrict__ dtsb,
                            const float* __restrict__ dtdW, const float* __restrict__ dtdb,
                            const float* __restrict__ BW,   const float* __restrict__ CrW,
                            const float* __restrict__ CiW) {
    int i = blockIdx.x * blockDim.x + threadIdx.x;
    if (i >= DIN * COLS_PAD) return;
    int k = i / COLS_PAD;
    int c = i % COLS_PAD;
    float v = 0.f;
    if      (c < 384) v = dtsW[c * DIN + k];
    else if (c < 768) v = dtdW[(c - 384) * DIN + k];
    else if (c < 784) v = BW [k * SST + (c - 768)];
    else if (c < 800) v = CrW[k * SST + (c - 784)];
    else if (c < 816) v = CiW[k * SST + (c - 800)];
    g_wpack[i] = v;
    if (k == 0) {
        float bv = 0.f;
        if (c < 384)      bv = dtsb[c];
        else if (c < 768) bv = dtdb[c - 384];
        g_bias[c] = bv;
    }
}

// ---------------- kernel 0b: transpose x -> xT[d][row] ----------------
__global__ void transpose_x(const float* __restrict__ x) {
    __shared__ float tile[32][33];
    int kb = blockIdx.x * 32;
    int rb = blockIdx.y * 32;
    int tx = threadIdx.x, ty = threadIdx.y;
    #pragma unroll
    for (int i = ty; i < 32; i += 8)
        tile[i][tx] = x[(rb + i) * DIN + kb + tx];
    __syncthreads();
    #pragma unroll
    for (int i = ty; i < 32; i += 8)
        g_xT[(kb + i) * NROWS + rb + tx] = tile[tx][i];
}

// ---------------- kernel 1: GEMM, 8x8 per thread, cp.async double-buffered ----------------
#define GBM 64
#define GBN 128
#define GBK 16
__global__ __launch_bounds__(128) void gemm_kernel() {
    __shared__ float Ws[2][GBK][68];
    __shared__ float Xs[2][GBK][GBN + 4];
    int tid = threadIdx.x;
    int tx = tid & 15;
    int ty = tid >> 4;
    int cBase = blockIdx.x * GBM;
    int rBase = blockIdx.y * GBN;

    f2 acc2[8][4];
    #pragma unroll
    for (int i = 0; i < 8; i++)
        #pragma unroll
        for (int j = 0; j < 4; j++) acc2[i][j] = pk(0.f, 0.f);

    // per-thread load slots (fixed across tiles)
    int wkk[2], wcc[2], xkk[4], xrr[4];
    #pragma unroll
    for (int ch = 0; ch < 2; ch++) {
        int idx = tid + ch * 128;
        wkk[ch] = idx >> 4; wcc[ch] = (idx & 15) * 4;
    }
    #pragma unroll
    for (int ch = 0; ch < 4; ch++) {
        int idx = tid + ch * 128;
        xkk[ch] = idx >> 5; xrr[ch] = (idx & 31) * 4;
    }

    // prologue: load tile 0 into buf 0
    #pragma unroll
    for (int ch = 0; ch < 2; ch++)
        cpa16(&Ws[0][wkk[ch]][wcc[ch]], &g_wpack[wkk[ch] * COLS_PAD + cBase + wcc[ch]]);
    #pragma unroll
    for (int ch = 0; ch < 4; ch++)
        cpa16(&Xs[0][xkk[ch]][xrr[ch]], &g_xT[xkk[ch] * NROWS + rBase + xrr[ch]]);
    cpa_commit();
    cpa_wait0();
    __syncthreads();

    int cur = 0;
    for (int kB = 0; kB < DIN; kB += GBK) {
        int nxt = cur ^ 1;
        int kN = kB + GBK;
        if (kN < DIN) {   // issue next-tile loads before computing (overlap)
            #pragma unroll
            for (int ch = 0; ch < 2; ch++)
                cpa16(&Ws[nxt][wkk[ch]][wcc[ch]],
                      &g_wpack[(kN + wkk[ch]) * COLS_PAD + cBase + wcc[ch]]);
            #pragma unroll
            for (int ch = 0; ch < 4; ch++)
                cpa16(&Xs[nxt][xkk[ch]][xrr[ch]],
                      &g_xT[(kN + xkk[ch]) * NROWS + rBase + xrr[ch]]);
            cpa_commit();
        }
        #pragma unroll
        for (int kk = 0; kk < GBK; kk++) {
            float a[8];
            *(float4*)&a[0] = *(const float4*)&Ws[cur][kk][ty * 8];
            *(float4*)&a[4] = *(const float4*)&Ws[cur][kk][ty * 8 + 4];
            float4 x0 = *(const float4*)&Xs[cur][kk][tx * 4];
            float4 x1 = *(const float4*)&Xs[cur][kk][64 + tx * 4];
            f2 b2[4] = { pk(x0.x, x0.y), pk(x0.z, x0.w), pk(x1.x, x1.y), pk(x1.z, x1.w) };
            #pragma unroll
            for (int i = 0; i < 8; i++) {
                f2 a2 = pk(a[i], a[i]);
                #pragma unroll
                for (int j = 0; j < 4; j++)
                    acc2[i][j] = fma2(a2, b2[j], acc2[i][j]);
            }
        }
        cpa_wait0();
        __syncthreads();
        cur = nxt;
    }

    #pragma unroll
    for (int i = 0; i < 8; i++) {
        int c = cBase + ty * 8 + i;
        float bv = g_bias[c];
        bool act = (c < 768);
        float o[8];
        #pragma unroll
        for (int j = 0; j < 4; j++) up2(acc2[i][j], o[2 * j], o[2 * j + 1]);
        #pragma unroll
        for (int j = 0; j < 8; j++) {
            float v = o[j];
            if (act) v = fminf(softplusf(v + bv), 0.15f);
            o[j] = v;
        }
        *(float4*)&g_scratch[c * NROWS + rBase + tx * 4]      = *(float4*)&o[0];
        *(float4*)&g_scratch[c * NROWS + rBase + 64 + tx * 4] = *(float4*)&o[4];
    }
}

// ---------------- kernel 2: SSM — R8 winner verbatim (scalar planes + SHFL edges, packed regs) ----------------
#define SHS 36
__global__ __launch_bounds__(128, 4) void ssm_kernel(const float* __restrict__ conv_w,
                                                     const float* __restrict__ ralpha,
                                                     const float* __restrict__ rbeta,
                                                     const float* __restrict__ Dparam,
                                                     const float* __restrict__ A_log,
                                                     float* __restrict__ y) {
    __shared__ float shR[2][32][SHS];
    __shared__ float shI[2][32][SHS];

    int d   = blockIdx.x;
    int b   = blockIdx.y;
    int t   = threadIdx.x;
    int R0  = (t >> 3) * 2;
    int lane8 = t & 7;
    int pcb = lane8 * 4;
    int row0 = b * NTOK;
    int n0 = R0 * 32 + pcb;
    int n1 = n0 + 32;

    int rm = (R0 > 0)      ? R0 - 1 : 0;
    int rp = (R0 + 2 < 32) ? R0 + 2 : 31;

    f2 w2[9];
    #pragma unroll
    for (int i = 0; i < 9; i++) { float wv = conv_w[d * 9 + i]; w2[i] = pk(wv, wv); }
    float alpha = ralpha[d];
    float beta  = rbeta[d];
    float Dp    = Dparam[d];
    const f2 HALF2 = pk(0.5f, 0.5f);

    float xv[8], yacc[8];
    f2 ds2[8], dd2[8];
    {
        float4 a = *(const float4*)&g_xT[d * NROWS + row0 + n0];
        float4 c = *(const float4*)&g_xT[d * NROWS + row0 + n1];
        xv[0]=a.x; xv[1]=a.y; xv[2]=a.z; xv[3]=a.w;
        xv[4]=c.x; xv[5]=c.y; xv[6]=c.z; xv[7]=c.w;
        a = *(const float4*)&g_scratch[d * NROWS + row0 + n0];
        c = *(const float4*)&g_scratch[d * NROWS + row0 + n1];
        ds2[0]=pk(a.x,a.x); ds2[1]=pk(a.y,a.y); ds2[2]=pk(a.z,a.z); ds2[3]=pk(a.w,a.w);
        ds2[4]=pk(c.x,c.x); ds2[5]=pk(c.y,c.y); ds2[6]=pk(c.z,c.z); ds2[7]=pk(c.w,c.w);
        a = *(const float4*)&g_scratch[(384 + d) * NROWS + row0 + n0];
        c = *(const float4*)&g_scratch[(384 + d) * NROWS + row0 + n1];
        dd2[0]=pk(a.x,a.x); dd2[1]=pk(a.y,a.y); dd2[2]=pk(a.z,a.z); dd2[3]=pk(a.w,a.w);
        dd2[4]=pk(c.x,c.x); dd2[5]=pk(c.y,c.y); dd2[6]=pk(c.z,c.z); dd2[7]=pk(c.w,c.w);
    }
    #pragma unroll
    for (int j = 0; j < 8; j++) yacc[j] = xv[j] * Dp;

    int buf = 0;
    for (int s = 0; s < SST; s++) {
        float A = -softplusf(A_log[d * SST + s]);
        f2 A2 = pk(A, A);
        f2 u2[8], hc[8];
        {
            float4 a = *(const float4*)&g_scratch[(768 + s) * NROWS + row0 + n0];
            float4 c = *(const float4*)&g_scratch[(768 + s) * NROWS + row0 + n1];
            u2[0] = pk(xv[0]*a.x, 0.f); u2[1] = pk(xv[1]*a.y, 0.f);
            u2[2] = pk(xv[2]*a.z, 0.f); u2[3] = pk(xv[3]*a.w, 0.f);
            u2[4] = pk(xv[4]*c.x, 0.f); u2[5] = pk(xv[5]*c.y, 0.f);
            u2[6] = pk(xv[6]*c.z, 0.f); u2[7] = pk(xv[7]*c.w, 0.f);
        }
        #pragma unroll
        for (int j = 0; j < 8; j++) hc[j] = u2[j];

        #pragma unroll
        for (int step = 0; step < 2; step++) {
            {
                float a0,b0,a1,b1,a2,b2,a3,b3;
                up2(hc[0],a0,b0); up2(hc[1],a1,b1); up2(hc[2],a2,b2); up2(hc[3],a3,b3);
                *(float4*)&shR[buf][R0][pcb] = make_float4(a0,a1,a2,a3);
                *(float4*)&shI[buf][R0][pcb] = make_float4(b0,b1,b2,b3);
                up2(hc[4],a0,b0); up2(hc[5],a1,b1); up2(hc[6],a2,b2); up2(hc[7],a3,b3);
                *(float4*)&shR[buf][R0+1][pcb] = make_float4(a0,a1,a2,a3);
                *(float4*)&shI[buf][R0+1][pcb] = make_float4(b0,b1,b2,b3);
            }
            __syncthreads();

            int cl = (pcb > 0)  ? pcb - 1 : 0;
            int cr = (pcb < 28) ? pcb + 4 : 31;
            float4 tR4 = *(const float4*)&shR[buf][rm][pcb];
            float4 tI4 = *(const float4*)&shI[buf][rm][pcb];
            float  tRl = shR[buf][rm][cl], tIl = shI[buf][rm][cl];
            float  tRr = shR[buf][rm][cr], tIr = shI[buf][rm][cr];
            float4 bR4 = *(const float4*)&shR[buf][rp][pcb];
            float4 bI4 = *(const float4*)&shI[buf][rp][pcb];
            float  bRl = shR[buf][rp][cl], bIl = shI[buf][rp][cl];
            float  bRr = shR[buf][rp][cr], bIr = shI[buf][rp][cr];

            float h0r,h0i,h3r,h3i,h4r,h4i,h7r,h7i;
            up2(hc[0],h0r,h0i); up2(hc[3],h3r,h3i);
            up2(hc[4],h4r,h4i); up2(hc[7],h7r,h7i);
            float e0lr = __shfl_up_sync(0xffffffffu,   h3r, 1);
            float e0li = __shfl_up_sync(0xffffffffu,   h3i, 1);
            float e0rr = __shfl_down_sync(0xffffffffu, h0r, 1);
            float e0ri = __shfl_down_sync(0xffffffffu, h0i, 1);
            float e1lr = __shfl_up_sync(0xffffffffu,   h7r, 1);
            float e1li = __shfl_up_sync(0xffffffffu,   h7i, 1);
            float e1rr = __shfl_down_sync(0xffffffffu, h4r, 1);
            float e1ri = __shfl_down_sync(0xffffffffu, h4i, 1);
            if (lane8 == 0) { e0lr=h0r; e0li=h0i; e1lr=h4r; e1li=h4i; }
            if (lane8 == 7) { e0rr=h3r; e0ri=h3i; e1rr=h7r; e1ri=h7i; }

            f2 T[6]  = { pk(tRl,tIl), pk(tR4.x,tI4.x), pk(tR4.y,tI4.y),
                         pk(tR4.z,tI4.z), pk(tR4.w,tI4.w), pk(tRr,tIr) };
            f2 Bw[6] = { pk(bRl,bIl), pk(bR4.x,bI4.x), pk(bR4.y,bI4.y),
                         pk(bR4.z,bI4.z), pk(bR4.w,bI4.w), pk(bRr,bIr) };
            f2 M0[6] = { pk(e0lr,e0li), hc[0], hc[1], hc[2], hc[3], pk(e0rr,e0ri) };
            f2 M1[6] = { pk(e1lr,e1li), hc[4], hc[5], hc[6], hc[7], pk(e1rr,e1ri) };

            f2 hn[8];
            #pragma unroll
            for (int c = 0; c < 4; c++) {
                f2 lap = mul2(w2[0], T[c]);
                lap = fma2(w2[1], T[c+1], lap);
                lap = fma2(w2[2], T[c+2], lap);
                lap = fma2(w2[3], M0[c],   lap);
                lap = fma2(w2[4], M0[c+1], lap);
                lap = fma2(w2[5], M0[c+2], lap);
                lap = fma2(w2[6], M1[c],   lap);
                lap = fma2(w2[7], M1[c+1], lap);
                lap = fma2(w2[8], M1[c+2], lap);
                {
                    float hrj, hij; up2(hc[c], hrj, hij);
                    float h2 = fmaf(hrj, hrj, hij * hij);
                    float rs = fmaf(-beta, h2, alpha);
                    f2 f1 = mul2(ds2[c], fma2(A2, hc[c], u2[c]));
                    float lr, li; up2(lap, lr, li);
                    f2 sum = fma2(dd2[c], pk(-li, lr), f1);
                    sum = fma2(hc[c], pk(rs, rs), sum);
                    hn[c] = fma2(HALF2, sum, hc[c]);
                }
                f2 lap2 = mul2(w2[0], M0[c]);
                lap2 = fma2(w2[1], M0[c+1], lap2);
                lap2 = fma2(w2[2], M0[c+2], lap2);
                lap2 = fma2(w2[3], M1[c],   lap2);
                lap2 = fma2(w2[4], M1[c+1], lap2);
                lap2 = fma2(w2[5], M1[c+2], lap2);
                lap2 = fma2(w2[6], Bw[c],   lap2);
                lap2 = fma2(w2[7], Bw[c+1], lap2);
                lap2 = fma2(w2[8], Bw[c+2], lap2);
                {
                    int j = 4 + c;
                    float hrj, hij; up2(hc[j], hrj, hij);
                    float h2 = fmaf(hrj, hrj, hij * hij);
                    float rs = fmaf(-beta, h2, alpha);
                    f2 f1 = mul2(ds2[j], fma2(A2, hc[j], u2[j]));
                    float lr, li; up2(lap2, lr, li);
                    f2 sum = fma2(dd2[j], pk(-li, lr), f1);
                    sum = fma2(hc[j], pk(rs, rs), sum);
                    hn[j] = fma2(HALF2, sum, hc[j]);
                }
            }
            #pragma unroll
            for (int j = 0; j < 8; j++) hc[j] = hn[j];
            buf ^= 1;
        }

        {
            float4 c0 = *(const float4*)&g_scratch[(784 + s) * NROWS + row0 + n0];
            float4 c1 = *(const float4*)&g_scratch[(784 + s) * NROWS + row0 + n1];
            float4 i0 = *(const float4*)&g_scratch[(800 + s) * NROWS + row0 + n0];
            float4 i1 = *(const float4*)&g_scratch[(800 + s) * NROWS + row0 + n1];
            float hr, hi;
            up2(hc[0], hr, hi); yacc[0] = fmaf(hr, c0.x, fmaf(hi, i0.x, yacc[0]));
            up2(hc[1], hr, hi); yacc[1] = fmaf(hr, c0.y, fmaf(hi, i0.y, yacc[1]));
            up2(hc[2], hr, hi); yacc[2] = fmaf(hr, c0.z, fmaf(hi, i0.z, yacc[2]));
            up2(hc[3], hr, hi); yacc[3] = fmaf(hr, c0.w, fmaf(hi, i0.w, yacc[3]));
            up2(hc[4], hr, hi); yacc[4] = fmaf(hr, c1.x, fmaf(hi, i1.x, yacc[4]));
            up2(hc[5], hr, hi); yacc[5] = fmaf(hr, c1.y, fmaf(hi, i1.y, yacc[5]));
            up2(hc[6], hr, hi); yacc[6] = fmaf(hr, c1.z, fmaf(hi, i1.z, yacc[6]));
            up2(hc[7], hr, hi); yacc[7] = fmaf(hr, c1.w, fmaf(hi, i1.w, yacc[7]));
        }
    }

    #pragma unroll
    for (int j = 0; j < 4; j++) {
        y[(row0 + n0 + j) * DIN + d] = yacc[j];
        y[(row0 + n1 + j) * DIN + d] = yacc[4 + j];
    }
}

// ---------------- launch ----------------
extern "C" void kernel_launch(void* const* d_in, const int* in_sizes, int n_in,
                              void* d_out, int out_size) {
    const float* x      = (const float*)d_in[0];
    const float* dtsW   = (const float*)d_in[1];
    const float* dtsb   = (const float*)d_in[2];
    const float* dtdW   = (const float*)d_in[3];
    const float* dtdb   = (const float*)d_in[4];
    const float* BW     = (const float*)d_in[5];
    const float* CrW    = (const float*)d_in[6];
    const float* CiW    = (const float*)d_in[7];
    const float* Dparam = (const float*)d_in[8];
    const float* A_log  = (const float*)d_in[9];
    const float* conv_w = (const float*)d_in[10];
    const float* ralpha = (const float*)d_in[11];
    const float* rbeta  = (const float*)d_in[12];
    float* y = (float*)d_out;

    pack_kernel<<<(DIN * COLS_PAD + 255) / 256, 256>>>(dtsW, dtsb, dtdW, dtdb, BW, CrW, CiW);
    transpose_x<<<dim3(DIN / 32, NROWS / 32), dim3(32, 8)>>>(x);
    gemm_kernel<<<dim3(COLS_PAD / GBM, NROWS / GBN), 128>>>();
    ssm_kernel<<<dim3(DIN, BSZ), 128>>>(conv_w, ralpha, rbeta, Dparam, A_log, y);
}

// round 12
// speedup vs baseline: 1.1954x; 1.1041x over previous
#include <cuda_runtime.h>
#include <cuda_bf16.h>
#include <math.h>

#define BSZ   4
#define NTOK  1024
#define DIN   384
#define SST   16
#define NROWS 4096
#define NCOLS 816
#define COLS_PAD 832
#define DTC   768          // dt columns (bf16 tensor path)

__device__ __align__(16) float g_wpack[DIN * COLS_PAD];
__device__ __align__(16) float g_bias[COLS_PAD];
__device__ __align__(16) float g_xT[DIN * NROWS];
__device__ __align__(16) float g_scratch[COLS_PAD * NROWS];
__device__ __align__(16) __nv_bfloat16 g_wbT[DTC * DIN];     // [c][k] bf16
__device__ __align__(16) __nv_bfloat16 g_xb[DIN * NROWS];    // [k][r] bf16

__device__ __forceinline__ float softplusf(float z) {
    return (z > 20.f) ? z : log1pf(expf(z));
}

// ---------------- packed f32x2 helpers ----------------
typedef unsigned long long f2;
__device__ __forceinline__ f2 pk(float lo, float hi) {
    f2 r; asm("mov.b64 %0,{%1,%2};" : "=l"(r) : "f"(lo), "f"(hi)); return r;
}
__device__ __forceinline__ void up2(f2 v, float& lo, float& hi) {
    asm("mov.b64 {%0,%1},%2;" : "=f"(lo), "=f"(hi) : "l"(v));
}
__device__ __forceinline__ f2 fma2(f2 a, f2 b, f2 c) {
    f2 r; asm("fma.rn.f32x2 %0,%1,%2,%3;" : "=l"(r) : "l"(a), "l"(b), "l"(c)); return r;
}
__device__ __forceinline__ f2 mul2(f2 a, f2 b) {
    f2 r; asm("mul.rn.f32x2 %0,%1,%2;" : "=l"(r) : "l"(a), "l"(b)); return r;
}

// ---------------- cp.async helpers ----------------
__device__ __forceinline__ void cpa16(void* smem_ptr, const void* gmem_ptr) {
    unsigned sa = (unsigned)__cvta_generic_to_shared(smem_ptr);
    asm volatile("cp.async.ca.shared.global [%0], [%1], 16;" :: "r"(sa), "l"(gmem_ptr));
}
__device__ __forceinline__ void cpa_commit() { asm volatile("cp.async.commit_group;"); }
__device__ __forceinline__ void cpa_wait0()  { asm volatile("cp.async.wait_group 0;"); }

// ---------------- kernel 0a: pack weights (fp32 full + bias) ----------------
__global__ void pack_kernel(const float* __restrict__ dtsW, const float* __restrict__ dtsb,
                            const float* __restrict__ dtdW, const float* __restrict__ dtdb,
                            const float* __restrict__ BW,   const float* __restrict__ CrW,
                            const float* __restrict__ CiW) {
    int i = blockIdx.x * blockDim.x + threadIdx.x;
    if (i >= DIN * COLS_PAD) return;
    int k = i / COLS_PAD;
    int c = i % COLS_PAD;
    float v = 0.f;
    if      (c < 384) v = dtsW[c * DIN + k];
    else if (c < 768) v = dtdW[(c - 384) * DIN + k];
    else if (c < 784) v = BW [k * SST + (c - 768)];
    else if (c < 800) v = CrW[k * SST + (c - 784)];
    else if (c < 816) v = CiW[k * SST + (c - 800)];
    g_wpack[i] = v;
    if (k == 0) {
        float bv = 0.f;
        if (c < 384)      bv = dtsb[c];
        else if (c < 768) bv = dtdb[c - 384];
        g_bias[c] = bv;
    }
}

// ---------------- kernel 0a': bf16 dt weights, [c][k] (coalesced both sides) ----------------
__global__ void pack_bf16(const float* __restrict__ dtsW, const float* __restrict__ dtdW) {
    int i = blockIdx.x * blockDim.x + threadIdx.x;
    if (i >= DTC * DIN) return;
    float v = (i < 384 * DIN) ? dtsW[i] : dtdW[i - 384 * DIN];
    g_wbT[i] = __float2bfloat16(v);
}

// ---------------- kernel 0b: transpose x -> xT (fp32) + xb (bf16) ----------------
__global__ void transpose_x(const float* __restrict__ x) {
    __shared__ float tile[32][33];
    int kb = blockIdx.x * 32;
    int rb = blockIdx.y * 32;
    int tx = threadIdx.x, ty = threadIdx.y;
    #pragma unroll
    for (int i = ty; i < 32; i += 8)
        tile[i][tx] = x[(rb + i) * DIN + kb + tx];
    __syncthreads();
    #pragma unroll
    for (int i = ty; i < 32; i += 8) {
        float v = tile[tx][i];
        g_xT[(kb + i) * NROWS + rb + tx] = v;
        g_xb[(kb + i) * NROWS + rb + tx] = __float2bfloat16(v);
    }
}

// ---------------- kernel 1a: dt-GEMM on tensor cores (bf16 mma.sync) ----------------
// Block 256 thr (8 warps), tile M=128 cols x N=128 rows x K=32. Warp: m64 x n32.
#define TAS 40    // A row stride in bf16 (80B: 16B-aligned, ldmatrix conflict-free)
#define TBS 136   // B row stride in bf16 (272B)
__global__ __launch_bounds__(256) void gemm_bf16() {
    __shared__ __align__(16) __nv_bfloat16 Ash[2][128][TAS];
    __shared__ __align__(16) __nv_bfloat16 Bsh[2][32][TBS];
    int tid = threadIdx.x;
    int lane = tid & 31;
    int w = tid >> 5;
    int warpM = (w & 1) * 64;
    int warpN = (w >> 1) * 32;
    int cBase = blockIdx.x * 128;
    int rBase = blockIdx.y * 128;

    float d[4][4][4];
    #pragma unroll
    for (int i = 0; i < 4; i++)
        #pragma unroll
        for (int j = 0; j < 4; j++)
            #pragma unroll
            for (int q = 0; q < 4; q++) d[i][j][q] = 0.f;

    // load-slot geometry (fixed)
    int am[2], ako[2], bk[2], bno[2];
    #pragma unroll
    for (int ch = 0; ch < 2; ch++) {
        int c = tid + ch * 256;
        am[ch] = c >> 2;  ako[ch] = (c & 3) * 8;     // A: 128 rows x 4 chunks of 8 bf16
        bk[ch] = c >> 4;  bno[ch] = (c & 15) * 8;    // B: 32 rows x 16 chunks
    }

    // prologue: tile 0 -> buf 0
    #pragma unroll
    for (int ch = 0; ch < 2; ch++) {
        cpa16(&Ash[0][am[ch]][ako[ch]], &g_wbT[(cBase + am[ch]) * DIN + ako[ch]]);
        cpa16(&Bsh[0][bk[ch]][bno[ch]], &g_xb[bk[ch] * NROWS + rBase + bno[ch]]);
    }
    cpa_commit();
    cpa_wait0();
    __syncthreads();

    int cur = 0;
    for (int kB = 0; kB < DIN; kB += 32) {
        int nxt = cur ^ 1;
        int kN = kB + 32;
        if (kN < DIN) {
            #pragma unroll
            for (int ch = 0; ch < 2; ch++) {
                cpa16(&Ash[nxt][am[ch]][ako[ch]], &g_wbT[(cBase + am[ch]) * DIN + kN + ako[ch]]);
                cpa16(&Bsh[nxt][bk[ch]][bno[ch]], &g_xb[(kN + bk[ch]) * NROWS + rBase + bno[ch]]);
            }
            cpa_commit();
        }
        #pragma unroll
        for (int kk = 0; kk < 32; kk += 16) {
            // A fragments: 4 m16 tiles
            unsigned a[4][4];
            #pragma unroll
            for (int mt = 0; mt < 4; mt++) {
                unsigned addr = (unsigned)__cvta_generic_to_shared(
                    &Ash[cur][warpM + mt * 16 + (lane & 15)][kk + (lane >> 4) * 8]);
                asm volatile("ldmatrix.sync.aligned.m8n8.x4.shared.b16 {%0,%1,%2,%3}, [%4];"
                    : "=r"(a[mt][0]), "=r"(a[mt][1]), "=r"(a[mt][2]), "=r"(a[mt][3]) : "r"(addr));
            }
            // B fragments: 2 n16 tiles (trans)
            unsigned bfr[2][4];
            #pragma unroll
            for (int nt2 = 0; nt2 < 2; nt2++) {
                unsigned addr = (unsigned)__cvta_generic_to_shared(
                    &Bsh[cur][kk + (lane & 15)][warpN + nt2 * 16 + (lane >> 4) * 8]);
                asm volatile("ldmatrix.sync.aligned.m8n8.x4.trans.shared.b16 {%0,%1,%2,%3}, [%4];"
                    : "=r"(bfr[nt2][0]), "=r"(bfr[nt2][1]), "=r"(bfr[nt2][2]), "=r"(bfr[nt2][3]) : "r"(addr));
            }
            #pragma unroll
            for (int mt = 0; mt < 4; mt++) {
                #pragma unroll
                for (int nt = 0; nt < 4; nt++) {
                    unsigned b0 = bfr[nt >> 1][(nt & 1) * 2 + 0];
                    unsigned b1 = bfr[nt >> 1][(nt & 1) * 2 + 1];
                    asm volatile(
                        "mma.sync.aligned.m16n8k16.row.col.f32.bf16.bf16.f32 "
                        "{%0,%1,%2,%3}, {%4,%5,%6,%7}, {%8,%9}, {%0,%1,%2,%3};"
                        : "+f"(d[mt][nt][0]), "+f"(d[mt][nt][1]), "+f"(d[mt][nt][2]), "+f"(d[mt][nt][3])
                        : "r"(a[mt][0]), "r"(a[mt][1]), "r"(a[mt][2]), "r"(a[mt][3]),
                          "r"(b0), "r"(b1));
                }
            }
        }
        cpa_wait0();
        __syncthreads();
        cur = nxt;
    }

    // epilogue: bias + softplus + clamp, transposed store (all cols here are dt cols)
    #pragma unroll
    for (int mt = 0; mt < 4; mt++) {
        int c0 = cBase + warpM + mt * 16 + (lane >> 2);
        float bv0 = g_bias[c0];
        float bv8 = g_bias[c0 + 8];
        #pragma unroll
        for (int nt = 0; nt < 4; nt++) {
            int r = rBase + warpN + nt * 8 + (lane & 3) * 2;
            float2 lo, hi;
            lo.x = fminf(softplusf(d[mt][nt][0] + bv0), 0.15f);
            lo.y = fminf(softplusf(d[mt][nt][1] + bv0), 0.15f);
            hi.x = fminf(softplusf(d[mt][nt][2] + bv8), 0.15f);
            hi.y = fminf(softplusf(d[mt][nt][3] + bv8), 0.15f);
            *(float2*)&g_scratch[c0 * NROWS + r]       = lo;
            *(float2*)&g_scratch[(c0 + 8) * NROWS + r] = hi;
        }
    }
}

// ---------------- kernel 1b: fp32 GEMM for B/C/Cr/Ci cols (768..831), cp.async ----------------
#define GBM 64
#define GBN 128
#define GBK 16
__global__ __launch_bounds__(128) void gemm_proj() {
    __shared__ float Ws[2][GBK][68];
    __shared__ float Xs[2][GBK][GBN + 4];
    int tid = threadIdx.x;
    int tx = tid & 15;
    int ty = tid >> 4;
    int cBase = DTC;                       // cols 768..831
    int rBase = blockIdx.y * GBN;

    f2 acc2[8][4];
    #pragma unroll
    for (int i = 0; i < 8; i++)
        #pragma unroll
        for (int j = 0; j < 4; j++) acc2[i][j] = pk(0.f, 0.f);

    int wkk[2], wcc[2], xkk[4], xrr[4];
    #pragma unroll
    for (int ch = 0; ch < 2; ch++) {
        int idx = tid + ch * 128;
        wkk[ch] = idx >> 4; wcc[ch] = (idx & 15) * 4;
    }
    #pragma unroll
    for (int ch = 0; ch < 4; ch++) {
        int idx = tid + ch * 128;
        xkk[ch] = idx >> 5; xrr[ch] = (idx & 31) * 4;
    }

    #pragma unroll
    for (int ch = 0; ch < 2; ch++)
        cpa16(&Ws[0][wkk[ch]][wcc[ch]], &g_wpack[wkk[ch] * COLS_PAD + cBase + wcc[ch]]);
    #pragma unroll
    for (int ch = 0; ch < 4; ch++)
        cpa16(&Xs[0][xkk[ch]][xrr[ch]], &g_xT[xkk[ch] * NROWS + rBase + xrr[ch]]);
    cpa_commit();
    cpa_wait0();
    __syncthreads();

    int cur = 0;
    for (int kB = 0; kB < DIN; kB += GBK) {
        int nxt = cur ^ 1;
        int kN = kB + GBK;
        if (kN < DIN) {
            #pragma unroll
            for (int ch = 0; ch < 2; ch++)
                cpa16(&Ws[nxt][wkk[ch]][wcc[ch]],
                      &g_wpack[(kN + wkk[ch]) * COLS_PAD + cBase + wcc[ch]]);
            #pragma unroll
            for (int ch = 0; ch < 4; ch++)
                cpa16(&Xs[nxt][xkk[ch]][xrr[ch]],
                      &g_xT[(kN + xkk[ch]) * NROWS + rBase + xrr[ch]]);
            cpa_commit();
        }
        #pragma unroll
        for (int kk = 0; kk < GBK; kk++) {
            float a[8];
            *(float4*)&a[0] = *(const float4*)&Ws[cur][kk][ty * 8];
            *(float4*)&a[4] = *(const float4*)&Ws[cur][kk][ty * 8 + 4];
            float4 x0 = *(const float4*)&Xs[cur][kk][tx * 4];
            float4 x1 = *(const float4*)&Xs[cur][kk][64 + tx * 4];
            f2 b2[4] = { pk(x0.x, x0.y), pk(x0.z, x0.w), pk(x1.x, x1.y), pk(x1.z, x1.w) };
            #pragma unroll
            for (int i = 0; i < 8; i++) {
                f2 a2 = pk(a[i], a[i]);
                #pragma unroll
                for (int j = 0; j < 4; j++)
                    acc2[i][j] = fma2(a2, b2[j], acc2[i][j]);
            }
        }
        cpa_wait0();
        __syncthreads();
        cur = nxt;
    }

    #pragma unroll
    for (int i = 0; i < 8; i++) {
        int c = cBase + ty * 8 + i;
        float o[8];
        #pragma unroll
        for (int j = 0; j < 4; j++) up2(acc2[i][j], o[2 * j], o[2 * j + 1]);
        *(float4*)&g_scratch[c * NROWS + rBase + tx * 4]      = *(float4*)&o[0];
        *(float4*)&g_scratch[c * NROWS + rBase + 64 + tx * 4] = *(float4*)&o[4];
    }
}

// ---------------- kernel 2: SSM — R8 winner (scalar planes + SHFL edges, packed regs) ----------------
#define SHS 36
__global__ __launch_bounds__(128, 4) void ssm_kernel(const float* __restrict__ conv_w,
                                                     const float* __restrict__ ralpha,
                                                     const float* __restrict__ rbeta,
                                                     const float* __restrict__ Dparam,
                                                     const float* __restrict__ A_log,
                                                     float* __restrict__ y) {
    __shared__ float shR[2][32][SHS];
    __shared__ float shI[2][32][SHS];

    int d   = blockIdx.x;
    int b   = blockIdx.y;
    int t   = threadIdx.x;
    int R0  = (t >> 3) * 2;
    int lane8 = t & 7;
    int pcb = lane8 * 4;
    int row0 = b * NTOK;
    int n0 = R0 * 32 + pcb;
    int n1 = n0 + 32;

    int rm = (R0 > 0)      ? R0 - 1 : 0;
    int rp = (R0 + 2 < 32) ? R0 + 2 : 31;

    f2 w2[9];
    #pragma unroll
    for (int i = 0; i < 9; i++) { float wv = conv_w[d * 9 + i]; w2[i] = pk(wv, wv); }
    float alpha = ralpha[d];
    float beta  = rbeta[d];
    float Dp    = Dparam[d];
    const f2 HALF2 = pk(0.5f, 0.5f);

    float xv[8], yacc[8];
    f2 ds2[8], dd2[8];
    {
        float4 a = *(const float4*)&g_xT[d * NROWS + row0 + n0];
        float4 c = *(const float4*)&g_xT[d * NROWS + row0 + n1];
        xv[0]=a.x; xv[1]=a.y; xv[2]=a.z; xv[3]=a.w;
        xv[4]=c.x; xv[5]=c.y; xv[6]=c.z; xv[7]=c.w;
        a = *(const float4*)&g_scratch[d * NROWS + row0 + n0];
        c = *(const float4*)&g_scratch[d * NROWS + row0 + n1];
        ds2[0]=pk(a.x,a.x); ds2[1]=pk(a.y,a.y); ds2[2]=pk(a.z,a.z); ds2[3]=pk(a.w,a.w);
        ds2[4]=pk(c.x,c.x); ds2[5]=pk(c.y,c.y); ds2[6]=pk(c.z,c.z); ds2[7]=pk(c.w,c.w);
        a = *(const float4*)&g_scratch[(384 + d) * NROWS + row0 + n0];
        c = *(const float4*)&g_scratch[(384 + d) * NROWS + row0 + n1];
        dd2[0]=pk(a.x,a.x); dd2[1]=pk(a.y,a.y); dd2[2]=pk(a.z,a.z); dd2[3]=pk(a.w,a.w);
        dd2[4]=pk(c.x,c.x); dd2[5]=pk(c.y,c.y); dd2[6]=pk(c.z,c.z); dd2[7]=pk(c.w,c.w);
    }
    #pragma unroll
    for (int j = 0; j < 8; j++) yacc[j] = xv[j] * Dp;

    int buf = 0;
    for (int s = 0; s < SST; s++) {
        float A = -softplusf(A_log[d * SST + s]);
        f2 A2 = pk(A, A);
        f2 u2[8], hc[8];
        {
            float4 a = *(const float4*)&g_scratch[(768 + s) * NROWS + row0 + n0];
            float4 c = *(const float4*)&g_scratch[(768 + s) * NROWS + row0 + n1];
            u2[0] = pk(xv[0]*a.x, 0.f); u2[1] = pk(xv[1]*a.y, 0.f);
            u2[2] = pk(xv[2]*a.z, 0.f); u2[3] = pk(xv[3]*a.w, 0.f);
            u2[4] = pk(xv[4]*c.x, 0.f); u2[5] = pk(xv[5]*c.y, 0.f);
            u2[6] = pk(xv[6]*c.z, 0.f); u2[7] = pk(xv[7]*c.w, 0.f);
        }
        #pragma unroll
        for (int j = 0; j < 8; j++) hc[j] = u2[j];

        #pragma unroll
        for (int step = 0; step < 2; step++) {
            {
                float a0,b0,a1,b1,a2,b2,a3,b3;
                up2(hc[0],a0,b0); up2(hc[1],a1,b1); up2(hc[2],a2,b2); up2(hc[3],a3,b3);
                *(float4*)&shR[buf][R0][pcb] = make_float4(a0,a1,a2,a3);
                *(float4*)&shI[buf][R0][pcb] = make_float4(b0,b1,b2,b3);
                up2(hc[4],a0,b0); up2(hc[5],a1,b1); up2(hc[6],a2,b2); up2(hc[7],a3,b3);
                *(float4*)&shR[buf][R0+1][pcb] = make_float4(a0,a1,a2,a3);
                *(float4*)&shI[buf][R0+1][pcb] = make_float4(b0,b1,b2,b3);
            }
            __syncthreads();

            int cl = (pcb > 0)  ? pcb - 1 : 0;
            int cr = (pcb < 28) ? pcb + 4 : 31;
            float4 tR4 = *(const float4*)&shR[buf][rm][pcb];
            float4 tI4 = *(const float4*)&shI[buf][rm][pcb];
            float  tRl = shR[buf][rm][cl], tIl = shI[buf][rm][cl];
            float  tRr = shR[buf][rm][cr], tIr = shI[buf][rm][cr];
            float4 bR4 = *(const float4*)&shR[buf][rp][pcb];
            float4 bI4 = *(const float4*)&shI[buf][rp][pcb];
            float  bRl = shR[buf][rp][cl], bIl = shI[buf][rp][cl];
            float  bRr = shR[buf][rp][cr], bIr = shI[buf][rp][cr];

            float h0r,h0i,h3r,h3i,h4r,h4i,h7r,h7i;
            up2(hc[0],h0r,h0i); up2(hc[3],h3r,h3i);
            up2(hc[4],h4r,h4i); up2(hc[7],h7r,h7i);
            float e0lr = __shfl_up_sync(0xffffffffu,   h3r, 1);
            float e0li = __shfl_up_sync(0xffffffffu,   h3i, 1);
            float e0rr = __shfl_down_sync(0xffffffffu, h0r, 1);
            float e0ri = __shfl_down_sync(0xffffffffu, h0i, 1);
            float e1lr = __shfl_up_sync(0xffffffffu,   h7r, 1);
            float e1li = __shfl_up_sync(0xffffffffu,   h7i, 1);
            float e1rr = __shfl_down_sync(0xffffffffu, h4r, 1);
            float e1ri = __shfl_down_sync(0xffffffffu, h4i, 1);
            if (lane8 == 0) { e0lr=h0r; e0li=h0i; e1lr=h4r; e1li=h4i; }
            if (lane8 == 7) { e0rr=h3r; e0ri=h3i; e1rr=h7r; e1ri=h7i; }

            f2 T[6]  = { pk(tRl,tIl), pk(tR4.x,tI4.x), pk(tR4.y,tI4.y),
                         pk(tR4.z,tI4.z), pk(tR4.w,tI4.w), pk(tRr,tIr) };
            f2 Bw[6] = { pk(bRl,bIl), pk(bR4.x,bI4.x), pk(bR4.y,bI4.y),
                         pk(bR4.z,bI4.z), pk(bR4.w,bI4.w), pk(bRr,bIr) };
            f2 M0[6] = { pk(e0lr,e0li), hc[0], hc[1], hc[2], hc[3], pk(e0rr,e0ri) };
            f2 M1[6] = { pk(e1lr,e1li), hc[4], hc[5], hc[6], hc[7], pk(e1rr,e1ri) };

            f2 hn[8];
            #pragma unroll
            for (int c = 0; c < 4; c++) {
                f2 lap = mul2(w2[0], T[c]);
                lap = fma2(w2[1], T[c+1], lap);
                lap = fma2(w2[2], T[c+2], lap);
                lap = fma2(w2[3], M0[c],   lap);
                lap = fma2(w2[4], M0[c+1], lap);
                lap = fma2(w2[5], M0[c+2], lap);
                lap = fma2(w2[6], M1[c],   lap);
                lap = fma2(w2[7], M1[c+1], lap);
                lap = fma2(w2[8], M1[c+2], lap);
                {
                    float hrj, hij; up2(hc[c], hrj, hij);
                    float h2 = fmaf(hrj, hrj, hij * hij);
                    float rs = fmaf(-beta, h2, alpha);
                    f2 f1 = mul2(ds2[c], fma2(A2, hc[c], u2[c]));
                    float lr, li; up2(lap, lr, li);
                    f2 sum = fma2(dd2[c], pk(-li, lr), f1);
                    sum = fma2(hc[c], pk(rs, rs), sum);
                    hn[c] = fma2(HALF2, sum, hc[c]);
                }
                f2 lap2 = mul2(w2[0], M0[c]);
                lap2 = fma2(w2[1], M0[c+1], lap2);
                lap2 = fma2(w2[2], M0[c+2], lap2);
                lap2 = fma2(w2[3], M1[c],   lap2);
                lap2 = fma2(w2[4], M1[c+1], lap2);
                lap2 = fma2(w2[5], M1[c+2], lap2);
                lap2 = fma2(w2[6], Bw[c],   lap2);
                lap2 = fma2(w2[7], Bw[c+1], lap2);
                lap2 = fma2(w2[8], Bw[c+2], lap2);
                {
                    int j = 4 + c;
                    float hrj, hij; up2(hc[j], hrj, hij);
                    float h2 = fmaf(hrj, hrj, hij * hij);
                    float rs = fmaf(-beta, h2, alpha);
                    f2 f1 = mul2(ds2[j], fma2(A2, hc[j], u2[j]));
                    float lr, li; up2(lap2, lr, li);
                    f2 sum = fma2(dd2[j], pk(-li, lr), f1);
                    sum = fma2(hc[j], pk(rs, rs), sum);
                    hn[j] = fma2(HALF2, sum, hc[j]);
                }
            }
            #pragma unroll
            for (int j = 0; j < 8; j++) hc[j] = hn[j];
            buf ^= 1;
        }

        {
            float4 c0 = *(const float4*)&g_scratch[(784 + s) * NROWS + row0 + n0];
            float4 c1 = *(const float4*)&g_scratch[(784 + s) * NROWS + row0 + n1];
            float4 i0 = *(const float4*)&g_scratch[(800 + s) * NROWS + row0 + n0];
            float4 i1 = *(const float4*)&g_scratch[(800 + s) * NROWS + row0 + n1];
            float hr, hi;
            up2(hc[0], hr, hi); yacc[0] = fmaf(hr, c0.x, fmaf(hi, i0.x, yacc[0]));
            up2(hc[1], hr, hi); yacc[1] = fmaf(hr, c0.y, fmaf(hi, i0.y, yacc[1]));
            up2(hc[2], hr, hi); yacc[2] = fmaf(hr, c0.z, fmaf(hi, i0.z, yacc[2]));
            up2(hc[3], hr, hi); yacc[3] = fmaf(hr, c0.w, fmaf(hi, i0.w, yacc[3]));
            up2(hc[4], hr, hi); yacc[4] = fmaf(hr, c1.x, fmaf(hi, i1.x, yacc[4]));
            up2(hc[5], hr, hi); yacc[5] = fmaf(hr, c1.y, fmaf(hi, i1.y, yacc[5]));
            up2(hc[6], hr, hi); yacc[6] = fmaf(hr, c1.z, fmaf(hi, i1.z, yacc[6]));
            up2(hc[7], hr, hi); yacc[7] = fmaf(hr, c1.w, fmaf(hi, i1.w, yacc[7]));
        }
    }

    #pragma unroll
    for (int j = 0; j < 4; j++) {
        y[(row0 + n0 + j) * DIN + d] = yacc[j];
        y[(row0 + n1 + j) * DIN + d] = yacc[4 + j];
    }
}

// ---------------- launch ----------------
extern "C" void kernel_launch(void* const* d_in, const int* in_sizes, int n_in,
                              void* d_out, int out_size) {
    const float* x      = (const float*)d_in[0];
    const float* dtsW   = (const float*)d_in[1];
    const float* dtsb   = (const float*)d_in[2];
    const float* dtdW   = (const float*)d_in[3];
    const float* dtdb   = (const float*)d_in[4];
    const float* BW     = (const float*)d_in[5];
    const float* CrW    = (const float*)d_in[6];
    const float* CiW    = (const float*)d_in[7];
    const float* Dparam = (const float*)d_in[8];
    const float* A_log  = (const float*)d_in[9];
    const float* conv_w = (const float*)d_in[10];
    const float* ralpha = (const float*)d_in[11];
    const float* rbeta  = (const float*)d_in[12];
    float* y = (float*)d_out;

    pack_kernel<<<(DIN * COLS_PAD + 255) / 256, 256>>>(dtsW, dtsb, dtdW, dtdb, BW, CrW, CiW);
    pack_bf16<<<(DTC * DIN + 255) / 256, 256>>>(dtsW, dtdW);
    transpose_x<<<dim3(DIN / 32, NROWS / 32), dim3(32, 8)>>>(x);
    gemm_bf16<<<dim3(DTC / 128, NROWS / 128), 256>>>();
    gemm_proj<<<dim3(1, NROWS / GBN), 128>>>();
    ssm_kernel<<<dim3(DIN, BSZ), 128>>>(conv_w, ralpha, rbeta, Dparam, A_log, y);
}

// round 15
// speedup vs baseline: 1.2300x; 1.0289x over previous
#include <cuda_runtime.h>
#include <cuda_bf16.h>
#include <math.h>

#define BSZ   4
#define NTOK  1024
#define DIN   384
#define SST   16
#define NROWS 4096
#define NCOLS 816
#define COLS_PAD 832
#define DTC   768

__device__ __align__(16) float g_wpack[DIN * COLS_PAD];
__device__ __align__(16) float g_bias[COLS_PAD];
__device__ __align__(16) float g_xT[DIN * NROWS];
__device__ __align__(16) float g_scratch[COLS_PAD * NROWS];
__device__ __align__(16) __nv_bfloat16 g_wbT[DTC * DIN];     // [c][k]
__device__ __align__(16) __nv_bfloat16 g_xb[DIN * NROWS];    // [k][r]

__device__ __forceinline__ float softplusf(float z) {
    return (z > 20.f) ? z : log1pf(expf(z));
}

// ---------------- packed f32x2 helpers ----------------
typedef unsigned long long f2;
__device__ __forceinline__ f2 pk(float lo, float hi) {
    f2 r; asm("mov.b64 %0,{%1,%2};" : "=l"(r) : "f"(lo), "f"(hi)); return r;
}
__device__ __forceinline__ void up2(f2 v, float& lo, float& hi) {
    asm("mov.b64 {%0,%1},%2;" : "=f"(lo), "=f"(hi) : "l"(v));
}
__device__ __forceinline__ f2 fma2(f2 a, f2 b, f2 c) {
    f2 r; asm("fma.rn.f32x2 %0,%1,%2,%3;" : "=l"(r) : "l"(a), "l"(b), "l"(c)); return r;
}
__device__ __forceinline__ f2 mul2(f2 a, f2 b) {
    f2 r; asm("mul.rn.f32x2 %0,%1,%2;" : "=l"(r) : "l"(a), "l"(b)); return r;
}

// ---------------- cp.async helpers ----------------
__device__ __forceinline__ void cpa16(void* smem_ptr, const void* gmem_ptr) {
    unsigned sa = (unsigned)__cvta_generic_to_shared(smem_ptr);
    asm volatile("cp.async.ca.shared.global [%0], [%1], 16;" :: "r"(sa), "l"(gmem_ptr));
}
__device__ __forceinline__ void cpa_commit() { asm volatile("cp.async.commit_group;"); }
__device__ __forceinline__ void cpa_wait0()  { asm volatile("cp.async.wait_group 0;"); }
__device__ __forceinline__ void cpa_wait1()  { asm volatile("cp.async.wait_group 1;"); }

// ---------------- kernel 0a: pack weights (fp32 + bias + bf16 dt) ----------------
__global__ void pack_kernel(const float* __restrict__ dtsW, const float* __restrict__ dtsb,
                            const float* __restrict__ dtdW, const float* __restrict__ dtdb,
                            const float* __restrict__ BW,   const float* __restrict__ CrW,
                            const float* __restrict__ CiW) {
    int i = blockIdx.x * blockDim.x + threadIdx.x;
    if (i < DTC * DIN) {    // bf16 dt weights [c][k]
        float v = (i < 384 * DIN) ? dtsW[i] : dtdW[i - 384 * DIN];
        g_wbT[i] = __float2bfloat16(v);
    }
    if (i >= DIN * COLS_PAD) return;
    int k = i / COLS_PAD;
    int c = i % COLS_PAD;
    float v = 0.f;
    if      (c < 384) v = dtsW[c * DIN + k];
    else if (c < 768) v = dtdW[(c - 384) * DIN + k];
    else if (c < 784) v = BW [k * SST + (c - 768)];
    else if (c < 800) v = CrW[k * SST + (c - 784)];
    else if (c < 816) v = CiW[k * SST + (c - 800)];
    g_wpack[i] = v;
    if (k == 0) {
        float bv = 0.f;
        if (c < 384)      bv = dtsb[c];
        else if (c < 768) bv = dtdb[c - 384];
        g_bias[c] = bv;
    }
}

// ---------------- kernel 0b: transpose x -> xT (fp32) + xb (bf16) ----------------
__global__ void transpose_x(const float* __restrict__ x) {
    __shared__ float tile[32][33];
    int kb = blockIdx.x * 32;
    int rb = blockIdx.y * 32;
    int tx = threadIdx.x, ty = threadIdx.y;
    #pragma unroll
    for (int i = ty; i < 32; i += 8)
        tile[i][tx] = x[(rb + i) * DIN + kb + tx];
    __syncthreads();
    #pragma unroll
    for (int i = ty; i < 32; i += 8) {
        float v = tile[tx][i];
        g_xT[(kb + i) * NROWS + rb + tx] = v;
        g_xb[(kb + i) * NROWS + rb + tx] = __float2bfloat16(v);
    }
}

// ---------------- kernel 1a: dt-GEMM tensor cores, 64x128 tile, 3-stage pipeline ----------------
#define TAS 40
#define TBS 136
#define NKT (DIN / 32)    // 12 k-tiles
__global__ __launch_bounds__(128) void gemm_bf16() {
    __shared__ __align__(16) __nv_bfloat16 Ash[3][64][TAS];
    __shared__ __align__(16) __nv_bfloat16 Bsh[3][32][TBS];
    int tid = threadIdx.x;
    int lane = tid & 31;
    int w = tid >> 5;                 // 4 warps
    int warpM = (w & 1) * 32;         // cols
    int warpN = (w >> 1) * 64;        // rows
    int cBase = blockIdx.x * 64;
    int rBase = blockIdx.y * 128;

    float d[2][8][4];
    #pragma unroll
    for (int i = 0; i < 2; i++)
        #pragma unroll
        for (int j = 0; j < 8; j++)
            #pragma unroll
            for (int q = 0; q < 4; q++) d[i][j][q] = 0.f;

    // load slots: A 64x4 chunks (2/thr), B 32x16 chunks (4/thr)
    int am[2], ako[2], bk[4], bno[4];
    #pragma unroll
    for (int ch = 0; ch < 2; ch++) {
        int c = tid + ch * 128;
        am[ch] = c >> 2; ako[ch] = (c & 3) * 8;
    }
    #pragma unroll
    for (int ch = 0; ch < 4; ch++) {
        int c = tid + ch * 128;
        bk[ch] = c >> 4; bno[ch] = (c & 15) * 8;
    }

    auto load_tile = [&](int stg, int kB) {
        #pragma unroll
        for (int ch = 0; ch < 2; ch++)
            cpa16(&Ash[stg][am[ch]][ako[ch]], &g_wbT[(cBase + am[ch]) * DIN + kB + ako[ch]]);
        #pragma unroll
        for (int ch = 0; ch < 4; ch++)
            cpa16(&Bsh[stg][bk[ch]][bno[ch]], &g_xb[(kB + bk[ch]) * NROWS + rBase + bno[ch]]);
        cpa_commit();
    };

    load_tile(0, 0);
    load_tile(1, 32);
    cpa_wait1();          // stage 0 complete
    __syncthreads();

    for (int t = 0; t < NKT; t++) {
        int cur = t % 3;
        if (t + 2 < NKT) load_tile((t + 2) % 3, (t + 2) * 32);
        #pragma unroll
        for (int kk = 0; kk < 32; kk += 16) {
            unsigned a[2][4];
            #pragma unroll
            for (int mt = 0; mt < 2; mt++) {
                unsigned addr = (unsigned)__cvta_generic_to_shared(
                    &Ash[cur][warpM + mt * 16 + (lane & 15)][kk + (lane >> 4) * 8]);
                asm volatile("ldmatrix.sync.aligned.m8n8.x4.shared.b16 {%0,%1,%2,%3}, [%4];"
                    : "=r"(a[mt][0]), "=r"(a[mt][1]), "=r"(a[mt][2]), "=r"(a[mt][3]) : "r"(addr));
            }
            unsigned bfr[4][4];
            #pragma unroll
            for (int nt2 = 0; nt2 < 4; nt2++) {
                unsigned addr = (unsigned)__cvta_generic_to_shared(
                    &Bsh[cur][kk + (lane & 15)][warpN + nt2 * 16 + (lane >> 4) * 8]);
                asm volatile("ldmatrix.sync.aligned.m8n8.x4.trans.shared.b16 {%0,%1,%2,%3}, [%4];"
                    : "=r"(bfr[nt2][0]), "=r"(bfr[nt2][1]), "=r"(bfr[nt2][2]), "=r"(bfr[nt2][3]) : "r"(addr));
            }
            #pragma unroll
            for (int mt = 0; mt < 2; mt++) {
                #pragma unroll
                for (int nt = 0; nt < 8; nt++) {
                    unsigned b0 = bfr[nt >> 1][(nt & 1) * 2 + 0];
                    unsigned b1 = bfr[nt >> 1][(nt & 1) * 2 + 1];
                    asm volatile(
                        "mma.sync.aligned.m16n8k16.row.col.f32.bf16.bf16.f32 "
                        "{%0,%1,%2,%3}, {%4,%5,%6,%7}, {%8,%9}, {%0,%1,%2,%3};"
                        : "+f"(d[mt][nt][0]), "+f"(d[mt][nt][1]), "+f"(d[mt][nt][2]), "+f"(d[mt][nt][3])
                        : "r"(a[mt][0]), "r"(a[mt][1]), "r"(a[mt][2]), "r"(a[mt][3]),
                          "r"(b0), "r"(b1));
                }
            }
        }
        if (t + 2 < NKT) cpa_wait1();
        else cpa_wait0();
        __syncthreads();
    }

    // epilogue: bias + softplus + clamp, transposed store
    #pragma unroll
    for (int mt = 0; mt < 2; mt++) {
        int c0 = cBase + warpM + mt * 16 + (lane >> 2);
        float bv0 = g_bias[c0];
        float bv8 = g_bias[c0 + 8];
        #pragma unroll
        for (int nt = 0; nt < 8; nt++) {
            int r = rBase + warpN + nt * 8 + (lane & 3) * 2;
            float2 lo, hi;
            lo.x = fminf(softplusf(d[mt][nt][0] + bv0), 0.15f);
            lo.y = fminf(softplusf(d[mt][nt][1] + bv0), 0.15f);
            hi.x = fminf(softplusf(d[mt][nt][2] + bv8), 0.15f);
            hi.y = fminf(softplusf(d[mt][nt][3] + bv8), 0.15f);
            *(float2*)&g_scratch[c0 * NROWS + r]       = lo;
            *(float2*)&g_scratch[(c0 + 8) * NROWS + r] = hi;
        }
    }
}

// ---------------- kernel 1b: fp32 GEMM for B/C/Cr/Ci cols (768..831) ----------------
#define GBM 64
#define GBN 128
#define GBK 16
__global__ __launch_bounds__(128) void gemm_proj() {
    __shared__ float Ws[2][GBK][68];
    __shared__ float Xs[2][GBK][GBN + 4];
    int tid = threadIdx.x;
    int tx = tid & 15;
    int ty = tid >> 4;
    int cBase = DTC;
    int rBase = blockIdx.y * GBN;

    f2 acc2[8][4];
    #pragma unroll
    for (int i = 0; i < 8; i++)
        #pragma unroll
        for (int j = 0; j < 4; j++) acc2[i][j] = pk(0.f, 0.f);

    int wkk[2], wcc[2], xkk[4], xrr[4];
    #pragma unroll
    for (int ch = 0; ch < 2; ch++) {
        int idx = tid + ch * 128;
        wkk[ch] = idx >> 4; wcc[ch] = (idx & 15) * 4;
    }
    #pragma unroll
    for (int ch = 0; ch < 4; ch++) {
        int idx = tid + ch * 128;
        xkk[ch] = idx >> 5; xrr[ch] = (idx & 31) * 4;
    }

    #pragma unroll
    for (int ch = 0; ch < 2; ch++)
        cpa16(&Ws[0][wkk[ch]][wcc[ch]], &g_wpack[wkk[ch] * COLS_PAD + cBase + wcc[ch]]);
    #pragma unroll
    for (int ch = 0; ch < 4; ch++)
        cpa16(&Xs[0][xkk[ch]][xrr[ch]], &g_xT[xkk[ch] * NROWS + rBase + xrr[ch]]);
    cpa_commit();
    cpa_wait0();
    __syncthreads();

    int cur = 0;
    for (int kB = 0; kB < DIN; kB += GBK) {
        int nxt = cur ^ 1;
        int kN = kB + GBK;
        if (kN < DIN) {
            #pragma unroll
            for (int ch = 0; ch < 2; ch++)
                cpa16(&Ws[nxt][wkk[ch]][wcc[ch]],
                      &g_wpack[(kN + wkk[ch]) * COLS_PAD + cBase + wcc[ch]]);
            #pragma unroll
            for (int ch = 0; ch < 4; ch++)
                cpa16(&Xs[nxt][xkk[ch]][xrr[ch]],
                      &g_xT[(kN + xkk[ch]) * NROWS + rBase + xrr[ch]]);
            cpa_commit();
        }
        #pragma unroll
        for (int kk = 0; kk < GBK; kk++) {
            float a[8];
            *(float4*)&a[0] = *(const float4*)&Ws[cur][kk][ty * 8];
            *(float4*)&a[4] = *(const float4*)&Ws[cur][kk][ty * 8 + 4];
            float4 x0 = *(const float4*)&Xs[cur][kk][tx * 4];
            float4 x1 = *(const float4*)&Xs[cur][kk][64 + tx * 4];
            f2 b2[4] = { pk(x0.x, x0.y), pk(x0.z, x0.w), pk(x1.x, x1.y), pk(x1.z, x1.w) };
            #pragma unroll
            for (int i = 0; i < 8; i++) {
                f2 a2 = pk(a[i], a[i]);
                #pragma unroll
                for (int j = 0; j < 4; j++)
                    acc2[i][j] = fma2(a2, b2[j], acc2[i][j]);
            }
        }
        cpa_wait0();
        __syncthreads();
        cur = nxt;
    }

    #pragma unroll
    for (int i = 0; i < 8; i++) {
        int c = cBase + ty * 8 + i;
        float o[8];
        #pragma unroll
        for (int j = 0; j < 4; j++) up2(acc2[i][j], o[2 * j], o[2 * j + 1]);
        *(float4*)&g_scratch[c * NROWS + rBase + tx * 4]      = *(float4*)&o[0];
        *(float4*)&g_scratch[c * NROWS + rBase + 64 + tx * 4] = *(float4*)&o[4];
    }
}

// ---------------- kernel 2: SSM — R8 winner (unchanged) ----------------
#define SHS 36
__global__ __launch_bounds__(128, 4) void ssm_kernel(const float* __restrict__ conv_w,
                                                     const float* __restrict__ ralpha,
                                                     const float* __restrict__ rbeta,
                                                     const float* __restrict__ Dparam,
                                                     const float* __restrict__ A_log,
                                                     float* __restrict__ y) {
    __shared__ float shR[2][32][SHS];
    __shared__ float shI[2][32][SHS];

    int d   = blockIdx.x;
    int b   = blockIdx.y;
    int t   = threadIdx.x;
    int R0  = (t >> 3) * 2;
    int lane8 = t & 7;
    int pcb = lane8 * 4;
    int row0 = b * NTOK;
    int n0 = R0 * 32 + pcb;
    int n1 = n0 + 32;

    int rm = (R0 > 0)      ? R0 - 1 : 0;
    int rp = (R0 + 2 < 32) ? R0 + 2 : 31;

    f2 w2[9];
    #pragma unroll
    for (int i = 0; i < 9; i++) { float wv = conv_w[d * 9 + i]; w2[i] = pk(wv, wv); }
    float alpha = ralpha[d];
    float beta  = rbeta[d];
    float Dp    = Dparam[d];
    const f2 HALF2 = pk(0.5f, 0.5f);

    float xv[8], yacc[8];
    f2 ds2[8], dd2[8];
    {
        float4 a = *(const float4*)&g_xT[d * NROWS + row0 + n0];
        float4 c = *(const float4*)&g_xT[d * NROWS + row0 + n1];
        xv[0]=a.x; xv[1]=a.y; xv[2]=a.z; xv[3]=a.w;
        xv[4]=c.x; xv[5]=c.y; xv[6]=c.z; xv[7]=c.w;
        a = *(const float4*)&g_scratch[d * NROWS + row0 + n0];
        c = *(const float4*)&g_scratch[d * NROWS + row0 + n1];
        ds2[0]=pk(a.x,a.x); ds2[1]=pk(a.y,a.y); ds2[2]=pk(a.z,a.z); ds2[3]=pk(a.w,a.w);
        ds2[4]=pk(c.x,c.x); ds2[5]=pk(c.y,c.y); ds2[6]=pk(c.z,c.z); ds2[7]=pk(c.w,c.w);
        a = *(const float4*)&g_scratch[(384 + d) * NROWS + row0 + n0];
        c = *(const float4*)&g_scratch[(384 + d) * NROWS + row0 + n1];
        dd2[0]=pk(a.x,a.x); dd2[1]=pk(a.y,a.y); dd2[2]=pk(a.z,a.z); dd2[3]=pk(a.w,a.w);
        dd2[4]=pk(c.x,c.x); dd2[5]=pk(c.y,c.y); dd2[6]=pk(c.z,c.z); dd2[7]=pk(c.w,c.w);
    }
    #pragma unroll
    for (int j = 0; j < 8; j++) yacc[j] = xv[j] * Dp;

    int buf = 0;
    for (int s = 0; s < SST; s++) {
        float A = -softplusf(A_log[d * SST + s]);
        f2 A2 = pk(A, A);
        f2 u2[8], hc[8];
        {
            float4 a = *(const float4*)&g_scratch[(768 + s) * NROWS + row0 + n0];
            float4 c = *(const float4*)&g_scratch[(768 + s) * NROWS + row0 + n1];
            u2[0] = pk(xv[0]*a.x, 0.f); u2[1] = pk(xv[1]*a.y, 0.f);
            u2[2] = pk(xv[2]*a.z, 0.f); u2[3] = pk(xv[3]*a.w, 0.f);
            u2[4] = pk(xv[4]*c.x, 0.f); u2[5] = pk(xv[5]*c.y, 0.f);
            u2[6] = pk(xv[6]*c.z, 0.f); u2[7] = pk(xv[7]*c.w, 0.f);
        }
        #pragma unroll
        for (int j = 0; j < 8; j++) hc[j] = u2[j];

        #pragma unroll
        for (int step = 0; step < 2; step++) {
            {
                float a0,b0,a1,b1,a2,b2,a3,b3;
                up2(hc[0],a0,b0); up2(hc[1],a1,b1); up2(hc[2],a2,b2); up2(hc[3],a3,b3);
                *(float4*)&shR[buf][R0][pcb] = make_float4(a0,a1,a2,a3);
                *(float4*)&shI[buf][R0][pcb] = make_float4(b0,b1,b2,b3);
                up2(hc[4],a0,b0); up2(hc[5],a1,b1); up2(hc[6],a2,b2); up2(hc[7],a3,b3);
                *(float4*)&shR[buf][R0+1][pcb] = make_float4(a0,a1,a2,a3);
                *(float4*)&shI[buf][R0+1][pcb] = make_float4(b0,b1,b2,b3);
            }
            __syncthreads();

            int cl = (pcb > 0)  ? pcb - 1 : 0;
            int cr = (pcb < 28) ? pcb + 4 : 31;
            float4 tR4 = *(const float4*)&shR[buf][rm][pcb];
            float4 tI4 = *(const float4*)&shI[buf][rm][pcb];
            float  tRl = shR[buf][rm][cl], tIl = shI[buf][rm][cl];
            float  tRr = shR[buf][rm][cr], tIr = shI[buf][rm][cr];
            float4 bR4 = *(const float4*)&shR[buf][rp][pcb];
            float4 bI4 = *(const float4*)&shI[buf][rp][pcb];
            float  bRl = shR[buf][rp][cl], bIl = shI[buf][rp][cl];
            float  bRr = shR[buf][rp][cr], bIr = shI[buf][rp][cr];

            float h0r,h0i,h3r,h3i,h4r,h4i,h7r,h7i;
            up2(hc[0],h0r,h0i); up2(hc[3],h3r,h3i);
            up2(hc[4],h4r,h4i); up2(hc[7],h7r,h7i);
            float e0lr = __shfl_up_sync(0xffffffffu,   h3r, 1);
            float e0li = __shfl_up_sync(0xffffffffu,   h3i, 1);
            float e0rr = __shfl_down_sync(0xffffffffu, h0r, 1);
            float e0ri = __shfl_down_sync(0xffffffffu, h0i, 1);
            float e1lr = __shfl_up_sync(0xffffffffu,   h7r, 1);
            float e1li = __shfl_up_sync(0xffffffffu,   h7i, 1);
            float e1rr = __shfl_down_sync(0xffffffffu, h4r, 1);
            float e1ri = __shfl_down_sync(0xffffffffu, h4i, 1);
            if (lane8 == 0) { e0lr=h0r; e0li=h0i; e1lr=h4r; e1li=h4i; }
            if (lane8 == 7) { e0rr=h3r; e0ri=h3i; e1rr=h7r; e1ri=h7i; }

            f2 T[6]  = { pk(tRl,tIl), pk(tR4.x,tI4.x), pk(tR4.y,tI4.y),
                         pk(tR4.z,tI4.z), pk(tR4.w,tI4.w), pk(tRr,tIr) };
            f2 Bw[6] = { pk(bRl,bIl), pk(bR4.x,bI4.x), pk(bR4.y,bI4.y),
                         pk(bR4.z,bI4.z), pk(bR4.w,bI4.w), pk(bRr,bIr) };
            f2 M0[6] = { pk(e0lr,e0li), hc[0], hc[1], hc[2], hc[3], pk(e0rr,e0ri) };
            f2 M1[6] = { pk(e1lr,e1li), hc[4], hc[5], hc[6], hc[7], pk(e1rr,e1ri) };

            f2 hn[8];
            #pragma unroll
            for (int c = 0; c < 4; c++) {
                f2 lap = mul2(w2[0], T[c]);
                lap = fma2(w2[1], T[c+1], lap);
                lap = fma2(w2[2], T[c+2], lap);
                lap = fma2(w2[3], M0[c],   lap);
                lap = fma2(w2[4], M0[c+1], lap);
                lap = fma2(w2[5], M0[c+2], lap);
                lap = fma2(w2[6], M1[c],   lap);
                lap = fma2(w2[7], M1[c+1], lap);
                lap = fma2(w2[8], M1[c+2], lap);
                {
                    float hrj, hij; up2(hc[c], hrj, hij);
                    float h2 = fmaf(hrj, hrj, hij * hij);
                    float rs = fmaf(-beta, h2, alpha);
                    f2 f1 = mul2(ds2[c], fma2(A2, hc[c], u2[c]));
                    float lr, li; up2(lap, lr, li);
                    f2 sum = fma2(dd2[c], pk(-li, lr), f1);
                    sum = fma2(hc[c], pk(rs, rs), sum);
                    hn[c] = fma2(HALF2, sum, hc[c]);
                }
                f2 lap2 = mul2(w2[0], M0[c]);
                lap2 = fma2(w2[1], M0[c+1], lap2);
                lap2 = fma2(w2[2], M0[c+2], lap2);
                lap2 = fma2(w2[3], M1[c],   lap2);
                lap2 = fma2(w2[4], M1[c+1], lap2);
                lap2 = fma2(w2[5], M1[c+2], lap2);
                lap2 = fma2(w2[6], Bw[c],   lap2);
                lap2 = fma2(w2[7], Bw[c+1], lap2);
                lap2 = fma2(w2[8], Bw[c+2], lap2);
                {
                    int j = 4 + c;
                    float hrj, hij; up2(hc[j], hrj, hij);
                    float h2 = fmaf(hrj, hrj, hij * hij);
                    float rs = fmaf(-beta, h2, alpha);
                    f2 f1 = mul2(ds2[j], fma2(A2, hc[j], u2[j]));
                    float lr, li; up2(lap2, lr, li);
                    f2 sum = fma2(dd2[j], pk(-li, lr), f1);
                    sum = fma2(hc[j], pk(rs, rs), sum);
                    hn[j] = fma2(HALF2, sum, hc[j]);
                }
            }
            #pragma unroll
            for (int j = 0; j < 8; j++) hc[j] = hn[j];
            buf ^= 1;
        }

        {
            float4 c0 = *(const float4*)&g_scratch[(784 + s) * NROWS + row0 + n0];
            float4 c1 = *(const float4*)&g_scratch[(784 + s) * NROWS + row0 + n1];
            float4 i0 = *(const float4*)&g_scratch[(800 + s) * NROWS + row0 + n0];
            float4 i1 = *(const float4*)&g_scratch[(800 + s) * NROWS + row0 + n1];
            float hr, hi;
            up2(hc[0], hr, hi); yacc[0] = fmaf(hr, c0.x, fmaf(hi, i0.x, yacc[0]));
            up2(hc[1], hr, hi); yacc[1] = fmaf(hr, c0.y, fmaf(hi, i0.y, yacc[1]));
            up2(hc[2], hr, hi); yacc[2] = fmaf(hr, c0.z, fmaf(hi, i0.z, yacc[2]));
            up2(hc[3], hr, hi); yacc[3] = fmaf(hr, c0.w, fmaf(hi, i0.w, yacc[3]));
            up2(hc[4], hr, hi); yacc[4] = fmaf(hr, c1.x, fmaf(hi, i1.x, yacc[4]));
            up2(hc[5], hr, hi); yacc[5] = fmaf(hr, c1.y, fmaf(hi, i1.y, yacc[5]));
            up2(hc[6], hr, hi); yacc[6] = fmaf(hr, c1.z, fmaf(hi, i1.z, yacc[6]));
            up2(hc[7], hr, hi); yacc[7] = fmaf(hr, c1.w, fmaf(hi, i1.w, yacc[7]));
        }
    }

    #pragma unroll
    for (int j = 0; j < 4; j++) {
        y[(row0 + n0 + j) * DIN + d] = yacc[j];
        y[(row0 + n1 + j) * DIN + d] = yacc[4 + j];
    }
}

// ---------------- launch ----------------
extern "C" void kernel_launch(void* const* d_in, const int* in_sizes, int n_in,
                              void* d_out, int out_size) {
    const float* x      = (const float*)d_in[0];
    const float* dtsW   = (const float*)d_in[1];
    const float* dtsb   = (const float*)d_in[2];
    const float* dtdW   = (const float*)d_in[3];
    const float* dtdb   = (const float*)d_in[4];
    const float* BW     = (const float*)d_in[5];
    const float* CrW    = (const float*)d_in[6];
    const float* CiW    = (const float*)d_in[7];
    const float* Dparam = (const float*)d_in[8];
    const float* A_log  = (const float*)d_in[9];
    const float* conv_w = (const float*)d_in[10];
    const float* ralpha = (const float*)d_in[11];
    const float* rbeta  = (const float*)d_in[12];
    float* y = (float*)d_out;

    pack_kernel<<<(DIN * COLS_PAD + 255) / 256, 256>>>(dtsW, dtsb, dtdW, dtdb, BW, CrW, CiW);
    transpose_x<<<dim3(DIN / 32, NROWS / 32), dim3(32, 8)>>>(x);
    gemm_bf16<<<dim3(DTC / 64, NROWS / 128), 128>>>();
    gemm_proj<<<dim3(1, NROWS / GBN), 128>>>();
    ssm_kernel<<<dim3(DIN, BSZ), 128>>>(conv_w, ralpha, rbeta, Dparam, A_log, y);
}

// round 16
// speedup vs baseline: 1.3539x; 1.1008x over previous
#include <cuda_runtime.h>
#include <cuda_bf16.h>
#include <math.h>

#define BSZ   4
#define NTOK  1024
#define DIN   384
#define SST   16
#define NROWS 4096
#define NCOLS 816
#define COLS_PAD 832
#define DTC   768

__device__ __align__(16) float g_wpack[DIN * COLS_PAD];
__device__ __align__(16) float g_bias[COLS_PAD];
__device__ __align__(16) float g_xT[DIN * NROWS];
__device__ __align__(16) float g_scratch[COLS_PAD * NROWS];
__device__ __align__(16) __nv_bfloat16 g_wbT[DTC * DIN];     // [c][k]
__device__ __align__(16) __nv_bfloat16 g_xb[DIN * NROWS];    // [k][r]

__device__ __forceinline__ float softplusf(float z) {
    return (z > 20.f) ? z : log1pf(expf(z));
}

// ---------------- packed f32x2 helpers ----------------
typedef unsigned long long f2;
__device__ __forceinline__ f2 pk(float lo, float hi) {
    f2 r; asm("mov.b64 %0,{%1,%2};" : "=l"(r) : "f"(lo), "f"(hi)); return r;
}
__device__ __forceinline__ void up2(f2 v, float& lo, float& hi) {
    asm("mov.b64 {%0,%1},%2;" : "=f"(lo), "=f"(hi) : "l"(v));
}
__device__ __forceinline__ f2 fma2(f2 a, f2 b, f2 c) {
    f2 r; asm("fma.rn.f32x2 %0,%1,%2,%3;" : "=l"(r) : "l"(a), "l"(b), "l"(c)); return r;
}
__device__ __forceinline__ f2 mul2(f2 a, f2 b) {
    f2 r; asm("mul.rn.f32x2 %0,%1,%2;" : "=l"(r) : "l"(a), "l"(b)); return r;
}

// ---------------- cp.async helpers ----------------
__device__ __forceinline__ void cpa16(void* smem_ptr, const void* gmem_ptr) {
    unsigned sa = (unsigned)__cvta_generic_to_shared(smem_ptr);
    asm volatile("cp.async.ca.shared.global [%0], [%1], 16;" :: "r"(sa), "l"(gmem_ptr));
}
__device__ __forceinline__ void cpa_commit() { asm volatile("cp.async.commit_group;"); }
__device__ __forceinline__ void cpa_wait0()  { asm volatile("cp.async.wait_group 0;"); }
__device__ __forceinline__ void cpa_wait1()  { asm volatile("cp.async.wait_group 1;"); }

// ---------------- kernel 0a: pack weights (fp32 + bias + bf16 dt) ----------------
__global__ void pack_kernel(const float* __restrict__ dtsW, const float* __restrict__ dtsb,
                            const float* __restrict__ dtdW, const float* __restrict__ dtdb,
                            const float* __restrict__ BW,   const float* __restrict__ CrW,
                            const float* __restrict__ CiW) {
    int i = blockIdx.x * blockDim.x + threadIdx.x;
    if (i < DTC * DIN) {
        float v = (i < 384 * DIN) ? dtsW[i] : dtdW[i - 384 * DIN];
        g_wbT[i] = __float2bfloat16(v);
    }
    if (i >= DIN * COLS_PAD) return;
    int k = i / COLS_PAD;
    int c = i % COLS_PAD;
    float v = 0.f;
    if      (c < 384) v = dtsW[c * DIN + k];
    else if (c < 768) v = dtdW[(c - 384) * DIN + k];
    else if (c < 784) v = BW [k * SST + (c - 768)];
    else if (c < 800) v = CrW[k * SST + (c - 784)];
    else if (c < 816) v = CiW[k * SST + (c - 800)];
    g_wpack[i] = v;
    if (k == 0) {
        float bv = 0.f;
        if (c < 384)      bv = dtsb[c];
        else if (c < 768) bv = dtdb[c - 384];
        g_bias[c] = bv;
    }
}

// ---------------- kernel 0b: transpose x -> xT (fp32) + xb (bf16) ----------------
__global__ void transpose_x(const float* __restrict__ x) {
    __shared__ float tile[32][33];
    int kb = blockIdx.x * 32;
    int rb = blockIdx.y * 32;
    int tx = threadIdx.x, ty = threadIdx.y;
    #pragma unroll
    for (int i = ty; i < 32; i += 8)
        tile[i][tx] = x[(rb + i) * DIN + kb + tx];
    __syncthreads();
    #pragma unroll
    for (int i = ty; i < 32; i += 8) {
        float v = tile[tx][i];
        g_xT[(kb + i) * NROWS + rb + tx] = v;
        g_xb[(kb + i) * NROWS + rb + tx] = __float2bfloat16(v);
    }
}

// ---------------- kernel 1: FUSED GEMM — bf16 tensor blocks + fp32 proj blocks in one grid ----------------
// grid (14, 32): x<12 -> bf16 path (64 cols x 128 rows); x in {12,13} -> proj path (64 cols x 64 rows)
#define TAS 40
#define TBS 136
#define NKT (DIN / 32)
#define SM_BYTES 41472       // bf16 path: 3*64*40*2 + 3*32*136*2
__global__ __launch_bounds__(128) void gemm_fused() {
    __shared__ __align__(16) char sm[SM_BYTES];
    int tid = threadIdx.x;

    if (blockIdx.x < 12) {
        // ================= bf16 tensor path =================
        __nv_bfloat16 (*Ash)[64][TAS] = reinterpret_cast<__nv_bfloat16 (*)[64][TAS]>(sm);
        __nv_bfloat16 (*Bsh)[32][TBS] = reinterpret_cast<__nv_bfloat16 (*)[32][TBS]>(sm + 15360);
        int lane = tid & 31;
        int w = tid >> 5;
        int warpM = (w & 1) * 32;
        int warpN = (w >> 1) * 64;
        int cBase = blockIdx.x * 64;
        int rBase = blockIdx.y * 128;

        float d[2][8][4];
        #pragma unroll
        for (int i = 0; i < 2; i++)
            #pragma unroll
            for (int j = 0; j < 8; j++)
                #pragma unroll
                for (int q = 0; q < 4; q++) d[i][j][q] = 0.f;

        int am[2], ako[2], bk[4], bno[4];
        #pragma unroll
        for (int ch = 0; ch < 2; ch++) {
            int c = tid + ch * 128;
            am[ch] = c >> 2; ako[ch] = (c & 3) * 8;
        }
        #pragma unroll
        for (int ch = 0; ch < 4; ch++) {
            int c = tid + ch * 128;
            bk[ch] = c >> 4; bno[ch] = (c & 15) * 8;
        }

        auto load_tile = [&](int stg, int kB) {
            #pragma unroll
            for (int ch = 0; ch < 2; ch++)
                cpa16(&Ash[stg][am[ch]][ako[ch]], &g_wbT[(cBase + am[ch]) * DIN + kB + ako[ch]]);
            #pragma unroll
            for (int ch = 0; ch < 4; ch++)
                cpa16(&Bsh[stg][bk[ch]][bno[ch]], &g_xb[(kB + bk[ch]) * NROWS + rBase + bno[ch]]);
            cpa_commit();
        };

        load_tile(0, 0);
        load_tile(1, 32);
        cpa_wait1();
        __syncthreads();

        for (int t = 0; t < NKT; t++) {
            int cur = t % 3;
            if (t + 2 < NKT) load_tile((t + 2) % 3, (t + 2) * 32);
            #pragma unroll
            for (int kk = 0; kk < 32; kk += 16) {
                unsigned a[2][4];
                #pragma unroll
                for (int mt = 0; mt < 2; mt++) {
                    unsigned addr = (unsigned)__cvta_generic_to_shared(
                        &Ash[cur][warpM + mt * 16 + (lane & 15)][kk + (lane >> 4) * 8]);
                    asm volatile("ldmatrix.sync.aligned.m8n8.x4.shared.b16 {%0,%1,%2,%3}, [%4];"
                        : "=r"(a[mt][0]), "=r"(a[mt][1]), "=r"(a[mt][2]), "=r"(a[mt][3]) : "r"(addr));
                }
                unsigned bfr[4][4];
                #pragma unroll
                for (int nt2 = 0; nt2 < 4; nt2++) {
                    unsigned addr = (unsigned)__cvta_generic_to_shared(
                        &Bsh[cur][kk + (lane & 15)][warpN + nt2 * 16 + (lane >> 4) * 8]);
                    asm volatile("ldmatrix.sync.aligned.m8n8.x4.trans.shared.b16 {%0,%1,%2,%3}, [%4];"
                        : "=r"(bfr[nt2][0]), "=r"(bfr[nt2][1]), "=r"(bfr[nt2][2]), "=r"(bfr[nt2][3]) : "r"(addr));
                }
                #pragma unroll
                for (int mt = 0; mt < 2; mt++) {
                    #pragma unroll
                    for (int nt = 0; nt < 8; nt++) {
                        unsigned b0 = bfr[nt >> 1][(nt & 1) * 2 + 0];
                        unsigned b1 = bfr[nt >> 1][(nt & 1) * 2 + 1];
                        asm volatile(
                            "mma.sync.aligned.m16n8k16.row.col.f32.bf16.bf16.f32 "
                            "{%0,%1,%2,%3}, {%4,%5,%6,%7}, {%8,%9}, {%0,%1,%2,%3};"
                            : "+f"(d[mt][nt][0]), "+f"(d[mt][nt][1]), "+f"(d[mt][nt][2]), "+f"(d[mt][nt][3])
                            : "r"(a[mt][0]), "r"(a[mt][1]), "r"(a[mt][2]), "r"(a[mt][3]),
                              "r"(b0), "r"(b1));
                    }
                }
            }
            if (t + 2 < NKT) cpa_wait1();
            else cpa_wait0();
            __syncthreads();
        }

        #pragma unroll
        for (int mt = 0; mt < 2; mt++) {
            int c0 = cBase + warpM + mt * 16 + (lane >> 2);
            float bv0 = g_bias[c0];
            float bv8 = g_bias[c0 + 8];
            #pragma unroll
            for (int nt = 0; nt < 8; nt++) {
                int r = rBase + warpN + nt * 8 + (lane & 3) * 2;
                float2 lo, hi;
                lo.x = fminf(softplusf(d[mt][nt][0] + bv0), 0.15f);
                lo.y = fminf(softplusf(d[mt][nt][1] + bv0), 0.15f);
                hi.x = fminf(softplusf(d[mt][nt][2] + bv8), 0.15f);
                hi.y = fminf(softplusf(d[mt][nt][3] + bv8), 0.15f);
                *(float2*)&g_scratch[c0 * NROWS + r]       = lo;
                *(float2*)&g_scratch[(c0 + 8) * NROWS + r] = hi;
            }
        }
    } else {
        // ================= fp32 proj path: 64 cols x 64 rows =================
        float (*Ws)[16][68] = reinterpret_cast<float (*)[16][68]>(sm);
        float (*Xs)[16][68] = reinterpret_cast<float (*)[16][68]>(sm + 8704);
        int tx = tid & 15;
        int ty = tid >> 4;
        int rBase = blockIdx.y * 128 + (blockIdx.x - 12) * 64;

        f2 acc2[8][2];
        #pragma unroll
        for (int i = 0; i < 8; i++) { acc2[i][0] = pk(0.f, 0.f); acc2[i][1] = pk(0.f, 0.f); }

        int wkk[2], wcc[2];
        #pragma unroll
        for (int ch = 0; ch < 2; ch++) {
            int idx = tid + ch * 128;
            wkk[ch] = idx >> 4; wcc[ch] = (idx & 15) * 4;
        }

        #pragma unroll
        for (int ch = 0; ch < 2; ch++) {
            cpa16(&Ws[0][wkk[ch]][wcc[ch]], &g_wpack[wkk[ch] * COLS_PAD + DTC + wcc[ch]]);
            cpa16(&Xs[0][wkk[ch]][wcc[ch]], &g_xT[wkk[ch] * NROWS + rBase + wcc[ch]]);
        }
        cpa_commit();
        cpa_wait0();
        __syncthreads();

        int cur = 0;
        for (int kB = 0; kB < DIN; kB += 16) {
            int nxt = cur ^ 1;
            int kN = kB + 16;
            if (kN < DIN) {
                #pragma unroll
                for (int ch = 0; ch < 2; ch++) {
                    cpa16(&Ws[nxt][wkk[ch]][wcc[ch]],
                          &g_wpack[(kN + wkk[ch]) * COLS_PAD + DTC + wcc[ch]]);
                    cpa16(&Xs[nxt][wkk[ch]][wcc[ch]],
                          &g_xT[(kN + wkk[ch]) * NROWS + rBase + wcc[ch]]);
                }
                cpa_commit();
            }
            #pragma unroll
            for (int kk = 0; kk < 16; kk++) {
                float a[8];
                *(float4*)&a[0] = *(const float4*)&Ws[cur][kk][ty * 8];
                *(float4*)&a[4] = *(const float4*)&Ws[cur][kk][ty * 8 + 4];
                float4 x0 = *(const float4*)&Xs[cur][kk][tx * 4];
                f2 b2[2] = { pk(x0.x, x0.y), pk(x0.z, x0.w) };
                #pragma unroll
                for (int i = 0; i < 8; i++) {
                    f2 a2 = pk(a[i], a[i]);
                    acc2[i][0] = fma2(a2, b2[0], acc2[i][0]);
                    acc2[i][1] = fma2(a2, b2[1], acc2[i][1]);
                }
            }
            cpa_wait0();
            __syncthreads();
            cur = nxt;
        }

        #pragma unroll
        for (int i = 0; i < 8; i++) {
            int c = DTC + ty * 8 + i;
            float o[4];
            up2(acc2[i][0], o[0], o[1]);
            up2(acc2[i][1], o[2], o[3]);
            *(float4*)&g_scratch[c * NROWS + rBase + tx * 4] = *(float4*)&o[0];
        }
    }
}

// ---------------- kernel 2: SSM — R8 winner (unchanged) ----------------
#define SHS 36
__global__ __launch_bounds__(128, 4) void ssm_kernel(const float* __restrict__ conv_w,
                                                     const float* __restrict__ ralpha,
                                                     const float* __restrict__ rbeta,
                                                     const float* __restrict__ Dparam,
                                                     const float* __restrict__ A_log,
                                                     float* __restrict__ y) {
    __shared__ float shR[2][32][SHS];
    __shared__ float shI[2][32][SHS];

    int d   = blockIdx.x;
    int b   = blockIdx.y;
    int t   = threadIdx.x;
    int R0  = (t >> 3) * 2;
    int lane8 = t & 7;
    int pcb = lane8 * 4;
    int row0 = b * NTOK;
    int n0 = R0 * 32 + pcb;
    int n1 = n0 + 32;

    int rm = (R0 > 0)      ? R0 - 1 : 0;
    int rp = (R0 + 2 < 32) ? R0 + 2 : 31;

    f2 w2[9];
    #pragma unroll
    for (int i = 0; i < 9; i++) { float wv = conv_w[d * 9 + i]; w2[i] = pk(wv, wv); }
    float alpha = ralpha[d];
    float beta  = rbeta[d];
    float Dp    = Dparam[d];
    const f2 HALF2 = pk(0.5f, 0.5f);

    float xv[8], yacc[8];
    f2 ds2[8], dd2[8];
    {
        float4 a = *(const float4*)&g_xT[d * NROWS + row0 + n0];
        float4 c = *(const float4*)&g_xT[d * NROWS + row0 + n1];
        xv[0]=a.x; xv[1]=a.y; xv[2]=a.z; xv[3]=a.w;
        xv[4]=c.x; xv[5]=c.y; xv[6]=c.z; xv[7]=c.w;
        a = *(const float4*)&g_scratch[d * NROWS + row0 + n0];
        c = *(const float4*)&g_scratch[d * NROWS + row0 + n1];
        ds2[0]=pk(a.x,a.x); ds2[1]=pk(a.y,a.y); ds2[2]=pk(a.z,a.z); ds2[3]=pk(a.w,a.w);
        ds2[4]=pk(c.x,c.x); ds2[5]=pk(c.y,c.y); ds2[6]=pk(c.z,c.z); ds2[7]=pk(c.w,c.w);
        a = *(const float4*)&g_scratch[(384 + d) * NROWS + row0 + n0];
        c = *(const float4*)&g_scratch[(384 + d) * NROWS + row0 + n1];
        dd2[0]=pk(a.x,a.x); dd2[1]=pk(a.y,a.y); dd2[2]=pk(a.z,a.z); dd2[3]=pk(a.w,a.w);
        dd2[4]=pk(c.x,c.x); dd2[5]=pk(c.y,c.y); dd2[6]=pk(c.z,c.z); dd2[7]=pk(c.w,c.w);
    }
    #pragma unroll
    for (int j = 0; j < 8; j++) yacc[j] = xv[j] * Dp;

    int buf = 0;
    for (int s = 0; s < SST; s++) {
        float A = -softplusf(A_log[d * SST + s]);
        f2 A2 = pk(A, A);
        f2 u2[8], hc[8];
        {
            float4 a = *(const float4*)&g_scratch[(768 + s) * NROWS + row0 + n0];
            float4 c = *(const float4*)&g_scratch[(768 + s) * NROWS + row0 + n1];
            u2[0] = pk(xv[0]*a.x, 0.f); u2[1] = pk(xv[1]*a.y, 0.f);
            u2[2] = pk(xv[2]*a.z, 0.f); u2[3] = pk(xv[3]*a.w, 0.f);
            u2[4] = pk(xv[4]*c.x, 0.f); u2[5] = pk(xv[5]*c.y, 0.f);
            u2[6] = pk(xv[6]*c.z, 0.f); u2[7] = pk(xv[7]*c.w, 0.f);
        }
        #pragma unroll
        for (int j = 0; j < 8; j++) hc[j] = u2[j];

        #pragma unroll
        for (int step = 0; step < 2; step++) {
            {
                float a0,b0,a1,b1,a2,b2,a3,b3;
                up2(hc[0],a0,b0); up2(hc[1],a1,b1); up2(hc[2],a2,b2); up2(hc[3],a3,b3);
                *(float4*)&shR[buf][R0][pcb] = make_float4(a0,a1,a2,a3);
                *(float4*)&shI[buf][R0][pcb] = make_float4(b0,b1,b2,b3);
                up2(hc[4],a0,b0); up2(hc[5],a1,b1); up2(hc[6],a2,b2); up2(hc[7],a3,b3);
                *(float4*)&shR[buf][R0+1][pcb] = make_float4(a0,a1,a2,a3);
                *(float4*)&shI[buf][R0+1][pcb] = make_float4(b0,b1,b2,b3);
            }
            __syncthreads();

            int cl = (pcb > 0)  ? pcb - 1 : 0;
            int cr = (pcb < 28) ? pcb + 4 : 31;
            float4 tR4 = *(const float4*)&shR[buf][rm][pcb];
            float4 tI4 = *(const float4*)&shI[buf][rm][pcb];
            float  tRl = shR[buf][rm][cl], tIl = shI[buf][rm][cl];
            float  tRr = shR[buf][rm][cr], tIr = shI[buf][rm][cr];
            float4 bR4 = *(const float4*)&shR[buf][rp][pcb];
            float4 bI4 = *(const float4*)&shI[buf][rp][pcb];
            float  bRl = shR[buf][rp][cl], bIl = shI[buf][rp][cl];
            float  bRr = shR[buf][rp][cr], bIr = shI[buf][rp][cr];

            float h0r,h0i,h3r,h3i,h4r,h4i,h7r,h7i;
            up2(hc[0],h0r,h0i); up2(hc[3],h3r,h3i);
            up2(hc[4],h4r,h4i); up2(hc[7],h7r,h7i);
            float e0lr = __shfl_up_sync(0xffffffffu,   h3r, 1);
            float e0li = __shfl_up_sync(0xffffffffu,   h3i, 1);
            float e0rr = __shfl_down_sync(0xffffffffu, h0r, 1);
            float e0ri = __shfl_down_sync(0xffffffffu, h0i, 1);
            float e1lr = __shfl_up_sync(0xffffffffu,   h7r, 1);
            float e1li = __shfl_up_sync(0xffffffffu,   h7i, 1);
            float e1rr = __shfl_down_sync(0xffffffffu, h4r, 1);
            float e1ri = __shfl_down_sync(0xffffffffu, h4i, 1);
            if (lane8 == 0) { e0lr=h0r; e0li=h0i; e1lr=h4r; e1li=h4i; }
            if (lane8 == 7) { e0rr=h3r; e0ri=h3i; e1rr=h7r; e1ri=h7i; }

            f2 T[6]  = { pk(tRl,tIl), pk(tR4.x,tI4.x), pk(tR4.y,tI4.y),
                         pk(tR4.z,tI4.z), pk(tR4.w,tI4.w), pk(tRr,tIr) };
            f2 Bw[6] = { pk(bRl,bIl), pk(bR4.x,bI4.x), pk(bR4.y,bI4.y),
                         pk(bR4.z,bI4.z), pk(bR4.w,bI4.w), pk(bRr,bIr) };
            f2 M0[6] = { pk(e0lr,e0li), hc[0], hc[1], hc[2], hc[3], pk(e0rr,e0ri) };
            f2 M1[6] = { pk(e1lr,e1li), hc[4], hc[5], hc[6], hc[7], pk(e1rr,e1ri) };

            f2 hn[8];
            #pragma unroll
            for (int c = 0; c < 4; c++) {
                f2 lap = mul2(w2[0], T[c]);
                lap = fma2(w2[1], T[c+1], lap);
                lap = fma2(w2[2], T[c+2], lap);
                lap = fma2(w2[3], M0[c],   lap);
                lap = fma2(w2[4], M0[c+1], lap);
                lap = fma2(w2[5], M0[c+2], lap);
                lap = fma2(w2[6], M1[c],   lap);
                lap = fma2(w2[7], M1[c+1], lap);
                lap = fma2(w2[8], M1[c+2], lap);
                {
                    float hrj, hij; up2(hc[c], hrj, hij);
                    float h2 = fmaf(hrj, hrj, hij * hij);
                    float rs = fmaf(-beta, h2, alpha);
                    f2 f1 = mul2(ds2[c], fma2(A2, hc[c], u2[c]));
                    float lr, li; up2(lap, lr, li);
                    f2 sum = fma2(dd2[c], pk(-li, lr), f1);
                    sum = fma2(hc[c], pk(rs, rs), sum);
                    hn[c] = fma2(HALF2, sum, hc[c]);
                }
                f2 lap2 = mul2(w2[0], M0[c]);
                lap2 = fma2(w2[1], M0[c+1], lap2);
                lap2 = fma2(w2[2], M0[c+2], lap2);
                lap2 = fma2(w2[3], M1[c],   lap2);
                lap2 = fma2(w2[4], M1[c+1], lap2);
                lap2 = fma2(w2[5], M1[c+2], lap2);
                lap2 = fma2(w2[6], Bw[c],   lap2);
                lap2 = fma2(w2[7], Bw[c+1], lap2);
                lap2 = fma2(w2[8], Bw[c+2], lap2);
                {
                    int j = 4 + c;
                    float hrj, hij; up2(hc[j], hrj, hij);
                    float h2 = fmaf(hrj, hrj, hij * hij);
                    float rs = fmaf(-beta, h2, alpha);
                    f2 f1 = mul2(ds2[j], fma2(A2, hc[j], u2[j]));
                    float lr, li; up2(lap2, lr, li);
                    f2 sum = fma2(dd2[j], pk(-li, lr), f1);
                    sum = fma2(hc[j], pk(rs, rs), sum);
                    hn[j] = fma2(HALF2, sum, hc[j]);
                }
            }
            #pragma unroll
            for (int j = 0; j < 8; j++) hc[j] = hn[j];
            buf ^= 1;
        }

        {
            float4 c0 = *(const float4*)&g_scratch[(784 + s) * NROWS + row0 + n0];
            float4 c1 = *(const float4*)&g_scratch[(784 + s) * NROWS + row0 + n1];
            float4 i0 = *(const float4*)&g_scratch[(800 + s) * NROWS + row0 + n0];
            float4 i1 = *(const float4*)&g_scratch[(800 + s) * NROWS + row0 + n1];
            float hr, hi;
            up2(hc[0], hr, hi); yacc[0] = fmaf(hr, c0.x, fmaf(hi, i0.x, yacc[0]));
            up2(hc[1], hr, hi); yacc[1] = fmaf(hr, c0.y, fmaf(hi, i0.y, yacc[1]));
            up2(hc[2], hr, hi); yacc[2] = fmaf(hr, c0.z, fmaf(hi, i0.z, yacc[2]));
            up2(hc[3], hr, hi); yacc[3] = fmaf(hr, c0.w, fmaf(hi, i0.w, yacc[3]));
            up2(hc[4], hr, hi); yacc[4] = fmaf(hr, c1.x, fmaf(hi, i1.x, yacc[4]));
            up2(hc[5], hr, hi); yacc[5] = fmaf(hr, c1.y, fmaf(hi, i1.y, yacc[5]));
            up2(hc[6], hr, hi); yacc[6] = fmaf(hr, c1.z, fmaf(hi, i1.z, yacc[6]));
            up2(hc[7], hr, hi); yacc[7] = fmaf(hr, c1.w, fmaf(hi, i1.w, yacc[7]));
        }
    }

    #pragma unroll
    for (int j = 0; j < 4; j++) {
        y[(row0 + n0 + j) * DIN + d] = yacc[j];
        y[(row0 + n1 + j) * DIN + d] = yacc[4 + j];
    }
}

// ---------------- launch ----------------
extern "C" void kernel_launch(void* const* d_in, const int* in_sizes, int n_in,
                              void* d_out, int out_size) {
    const float* x      = (const float*)d_in[0];
    const float* dtsW   = (const float*)d_in[1];
    const float* dtsb   = (const float*)d_in[2];
    const float* dtdW   = (const float*)d_in[3];
    const float* dtdb   = (const float*)d_in[4];
    const float* BW     = (const float*)d_in[5];
    const float* CrW    = (const float*)d_in[6];
    const float* CiW    = (const float*)d_in[7];
    const float* Dparam = (const float*)d_in[8];
    const float* A_log  = (const float*)d_in[9];
    const float* conv_w = (const float*)d_in[10];
    const float* ralpha = (const float*)d_in[11];
    const float* rbeta  = (const float*)d_in[12];
    float* y = (float*)d_out;

    pack_kernel<<<(DIN * COLS_PAD + 255) / 256, 256>>>(dtsW, dtsb, dtdW, dtdb, BW, CrW, CiW);
    transpose_x<<<dim3(DIN / 32, NROWS / 32), dim3(32, 8)>>>(x);
    gemm_fused<<<dim3(14, NROWS / 128), 128>>>();
    ssm_kernel<<<dim3(DIN, BSZ), 128>>>(conv_w, ralpha, rbeta, Dparam, A_log, y);
}

// round 17
// speedup vs baseline: 1.3644x; 1.0077x over previous
#include <cuda_runtime.h>
#include <cuda_bf16.h>
#include <math.h>

#define BSZ   4
#define NTOK  1024
#define DIN   384
#define SST   16
#define NROWS 4096
#define NCOLS 816
#define COLS_PAD 832
#define DTC   768

__device__ __align__(16) float g_wpack[DIN * COLS_PAD];
__device__ __align__(16) float g_bias[COLS_PAD];
__device__ __align__(16) float g_xT[DIN * NROWS];
__device__ __align__(16) float g_scratch[COLS_PAD * NROWS];
__device__ __align__(16) __nv_bfloat16 g_wbT[DTC * DIN];     // [c][k]
__device__ __align__(16) __nv_bfloat16 g_xb[NROWS * DIN];    // [r][k] — same layout as x, just bf16

__device__ __forceinline__ float softplusf(float z) {
    return (z > 20.f) ? z : log1pf(expf(z));
}

// ---------------- packed f32x2 helpers ----------------
typedef unsigned long long f2;
__device__ __forceinline__ f2 pk(float lo, float hi) {
    f2 r; asm("mov.b64 %0,{%1,%2};" : "=l"(r) : "f"(lo), "f"(hi)); return r;
}
__device__ __forceinline__ void up2(f2 v, float& lo, float& hi) {
    asm("mov.b64 {%0,%1},%2;" : "=f"(lo), "=f"(hi) : "l"(v));
}
__device__ __forceinline__ f2 fma2(f2 a, f2 b, f2 c) {
    f2 r; asm("fma.rn.f32x2 %0,%1,%2,%3;" : "=l"(r) : "l"(a), "l"(b), "l"(c)); return r;
}
__device__ __forceinline__ f2 mul2(f2 a, f2 b) {
    f2 r; asm("mul.rn.f32x2 %0,%1,%2;" : "=l"(r) : "l"(a), "l"(b)); return r;
}

// ---------------- cp.async helpers ----------------
__device__ __forceinline__ void cpa16(void* smem_ptr, const void* gmem_ptr) {
    unsigned sa = (unsigned)__cvta_generic_to_shared(smem_ptr);
    asm volatile("cp.async.ca.shared.global [%0], [%1], 16;" :: "r"(sa), "l"(gmem_ptr));
}
__device__ __forceinline__ void cpa_commit() { asm volatile("cp.async.commit_group;"); }
__device__ __forceinline__ void cpa_wait0()  { asm volatile("cp.async.wait_group 0;"); }
__device__ __forceinline__ void cpa_wait1()  { asm volatile("cp.async.wait_group 1;"); }

// ---------------- kernel 0: prep — pack weights + convert x + transpose x, one grid ----------------
// blocks [0,1248): weight pack (fp32 + bias + bf16 dt)
// blocks [1248,2784): x -> g_xb bf16 convert ([r][k], coalesced float4)
// blocks [2784,4320): x -> g_xT fp32 transpose
#define PREP_PACK   1248
#define PREP_CONV   1536
#define PREP_TRANS  1536
__global__ __launch_bounds__(256) void prep_kernel(
        const float* __restrict__ x,
        const float* __restrict__ dtsW, const float* __restrict__ dtsb,
        const float* __restrict__ dtdW, const float* __restrict__ dtdb,
        const float* __restrict__ BW,   const float* __restrict__ CrW,
        const float* __restrict__ CiW) {
    __shared__ float tile[32][33];
    int bx = blockIdx.x;
    int tid = threadIdx.x;

    if (bx < PREP_PACK) {
        int i = bx * 256 + tid;
        if (i < DTC * DIN) {
            float v = (i < 384 * DIN) ? dtsW[i] : dtdW[i - 384 * DIN];
            g_wbT[i] = __float2bfloat16(v);
        }
        if (i >= DIN * COLS_PAD) return;
        int k = i / COLS_PAD;
        int c = i % COLS_PAD;
        float v = 0.f;
        if      (c < 384) v = dtsW[c * DIN + k];
        else if (c < 768) v = dtdW[(c - 384) * DIN + k];
        else if (c < 784) v = BW [k * SST + (c - 768)];
        else if (c < 800) v = CrW[k * SST + (c - 784)];
        else if (c < 816) v = CiW[k * SST + (c - 800)];
        g_wpack[i] = v;
        if (k == 0) {
            float bv = 0.f;
            if (c < 384)      bv = dtsb[c];
            else if (c < 768) bv = dtdb[c - 384];
            g_bias[c] = bv;
        }
    } else if (bx < PREP_PACK + PREP_CONV) {
        // elementwise fp32 -> bf16 (x and g_xb share layout)
        int i = (bx - PREP_PACK) * 256 + tid;      // float4 index, total 393216
        float4 v = ((const float4*)x)[i];
        __nv_bfloat162* o = (__nv_bfloat162*)g_xb;
        o[i * 2]     = __floats2bfloat162_rn(v.x, v.y);
        o[i * 2 + 1] = __floats2bfloat162_rn(v.z, v.w);
    } else {
        int idx = bx - (PREP_PACK + PREP_CONV);
        int kb = (idx % 12) * 32;
        int rb = (idx / 12) * 32;
        int tx = tid & 31, ty = tid >> 5;
        #pragma unroll
        for (int i = ty; i < 32; i += 8)
            tile[i][tx] = x[(rb + i) * DIN + kb + tx];
        __syncthreads();
        #pragma unroll
        for (int i = ty; i < 32; i += 8)
            g_xT[(kb + i) * NROWS + rb + tx] = tile[tx][i];
    }
}

// ---------------- kernel 1: FUSED GEMM — bf16 tensor blocks + fp32 proj blocks ----------------
// grid (14, 32): x<12 -> bf16 path; x in {12,13} -> proj path
#define TAS 40
#define TBS2 40            // B now [n][k], same lean stride as A
#define NKT (DIN / 32)
#define SM_BYTES 46080     // 3*64*40*2 + 3*128*40*2
__global__ __launch_bounds__(128) void gemm_fused() {
    __shared__ __align__(16) char sm[SM_BYTES];
    int tid = threadIdx.x;

    if (blockIdx.x < 12) {
        // ================= bf16 tensor path =================
        __nv_bfloat16 (*Ash)[64][TAS]  = reinterpret_cast<__nv_bfloat16 (*)[64][TAS]>(sm);
        __nv_bfloat16 (*Bsh)[128][TBS2] = reinterpret_cast<__nv_bfloat16 (*)[128][TBS2]>(sm + 15360);
        int lane = tid & 31;
        int w = tid >> 5;
        int warpM = (w & 1) * 32;
        int warpN = (w >> 1) * 64;
        int cBase = blockIdx.x * 64;
        int rBase = blockIdx.y * 128;

        float d[2][8][4];
        #pragma unroll
        for (int i = 0; i < 2; i++)
            #pragma unroll
            for (int j = 0; j < 8; j++)
                #pragma unroll
                for (int q = 0; q < 4; q++) d[i][j][q] = 0.f;

        int am[2], ako[2], br[4], bko[4];
        #pragma unroll
        for (int ch = 0; ch < 2; ch++) {
            int c = tid + ch * 128;
            am[ch] = c >> 2; ako[ch] = (c & 3) * 8;
        }
        #pragma unroll
        for (int ch = 0; ch < 4; ch++) {
            int c = tid + ch * 128;
            br[ch] = c >> 2; bko[ch] = (c & 3) * 8;
        }

        auto load_tile = [&](int stg, int kB) {
            #pragma unroll
            for (int ch = 0; ch < 2; ch++)
                cpa16(&Ash[stg][am[ch]][ako[ch]], &g_wbT[(cBase + am[ch]) * DIN + kB + ako[ch]]);
            #pragma unroll
            for (int ch = 0; ch < 4; ch++)
                cpa16(&Bsh[stg][br[ch]][bko[ch]], &g_xb[(rBase + br[ch]) * DIN + kB + bko[ch]]);
            cpa_commit();
        };

        load_tile(0, 0);
        load_tile(1, 32);
        cpa_wait1();
        __syncthreads();

        for (int t = 0; t < NKT; t++) {
            int cur = t % 3;
            if (t + 2 < NKT) load_tile((t + 2) % 3, (t + 2) * 32);
            #pragma unroll
            for (int kk = 0; kk < 32; kk += 16) {
                unsigned a[2][4];
                #pragma unroll
                for (int mt = 0; mt < 2; mt++) {
                    unsigned addr = (unsigned)__cvta_generic_to_shared(
                        &Ash[cur][warpM + mt * 16 + (lane & 15)][kk + (lane >> 4) * 8]);
                    asm volatile("ldmatrix.sync.aligned.m8n8.x4.shared.b16 {%0,%1,%2,%3}, [%4];"
                        : "=r"(a[mt][0]), "=r"(a[mt][1]), "=r"(a[mt][2]), "=r"(a[mt][3]) : "r"(addr));
                }
                // B: col-major [n][k] -> non-trans ldmatrix (r0/r2 = n0-7 k-halves, r1/r3 = n8-15)
                unsigned bfr[4][4];
                #pragma unroll
                for (int nt2 = 0; nt2 < 4; nt2++) {
                    unsigned addr = (unsigned)__cvta_generic_to_shared(
                        &Bsh[cur][warpN + nt2 * 16 + (lane & 15)][kk + (lane >> 4) * 8]);
                    asm volatile("ldmatrix.sync.aligned.m8n8.x4.shared.b16 {%0,%1,%2,%3}, [%4];"
                        : "=r"(bfr[nt2][0]), "=r"(bfr[nt2][1]), "=r"(bfr[nt2][2]), "=r"(bfr[nt2][3]) : "r"(addr));
                }
                #pragma unroll
                for (int mt = 0; mt < 2; mt++) {
                    #pragma unroll
                    for (int nt = 0; nt < 8; nt++) {
                        unsigned b0 = bfr[nt >> 1][(nt & 1)];
                        unsigned b1 = bfr[nt >> 1][(nt & 1) + 2];
                        asm volatile(
                            "mma.sync.aligned.m16n8k16.row.col.f32.bf16.bf16.f32 "
                            "{%0,%1,%2,%3}, {%4,%5,%6,%7}, {%8,%9}, {%0,%1,%2,%3};"
                            : "+f"(d[mt][nt][0]), "+f"(d[mt][nt][1]), "+f"(d[mt][nt][2]), "+f"(d[mt][nt][3])
                            : "r"(a[mt][0]), "r"(a[mt][1]), "r"(a[mt][2]), "r"(a[mt][3]),
                              "r"(b0), "r"(b1));
                    }
                }
            }
            if (t + 2 < NKT) cpa_wait1();
            else cpa_wait0();
            __syncthreads();
        }

        #pragma unroll
        for (int mt = 0; mt < 2; mt++) {
            int c0 = cBase + warpM + mt * 16 + (lane >> 2);
            float bv0 = g_bias[c0];
            float bv8 = g_bias[c0 + 8];
            #pragma unroll
            for (int nt = 0; nt < 8; nt++) {
                int r = rBase + warpN + nt * 8 + (lane & 3) * 2;
                float2 lo, hi;
                lo.x = fminf(softplusf(d[mt][nt][0] + bv0), 0.15f);
                lo.y = fminf(softplusf(d[mt][nt][1] + bv0), 0.15f);
                hi.x = fminf(softplusf(d[mt][nt][2] + bv8), 0.15f);
                hi.y = fminf(softplusf(d[mt][nt][3] + bv8), 0.15f);
                *(float2*)&g_scratch[c0 * NROWS + r]       = lo;
                *(float2*)&g_scratch[(c0 + 8) * NROWS + r] = hi;
            }
        }
    } else {
        // ================= fp32 proj path: 64 cols x 64 rows =================
        float (*Ws)[16][68] = reinterpret_cast<float (*)[16][68]>(sm);
        float (*Xs)[16][68] = reinterpret_cast<float (*)[16][68]>(sm + 8704);
        int tx = tid & 15;
        int ty = tid >> 4;
        int rBase = blockIdx.y * 128 + (blockIdx.x - 12) * 64;

        f2 acc2[8][2];
        #pragma unroll
        for (int i = 0; i < 8; i++) { acc2[i][0] = pk(0.f, 0.f); acc2[i][1] = pk(0.f, 0.f); }

        int wkk[2], wcc[2];
        #pragma unroll
        for (int ch = 0; ch < 2; ch++) {
            int idx = tid + ch * 128;
            wkk[ch] = idx >> 4; wcc[ch] = (idx & 15) * 4;
        }

        #pragma unroll
        for (int ch = 0; ch < 2; ch++) {
            cpa16(&Ws[0][wkk[ch]][wcc[ch]], &g_wpack[wkk[ch] * COLS_PAD + DTC + wcc[ch]]);
            cpa16(&Xs[0][wkk[ch]][wcc[ch]], &g_xT[wkk[ch] * NROWS + rBase + wcc[ch]]);
        }
        cpa_commit();
        cpa_wait0();
        __syncthreads();

        int cur = 0;
        for (int kB = 0; kB < DIN; kB += 16) {
            int nxt = cur ^ 1;
            int kN = kB + 16;
            if (kN < DIN) {
                #pragma unroll
                for (int ch = 0; ch < 2; ch++) {
                    cpa16(&Ws[nxt][wkk[ch]][wcc[ch]],
                          &g_wpack[(kN + wkk[ch]) * COLS_PAD + DTC + wcc[ch]]);
                    cpa16(&Xs[nxt][wkk[ch]][wcc[ch]],
                          &g_xT[(kN + wkk[ch]) * NROWS + rBase + wcc[ch]]);
                }
                cpa_commit();
            }
            #pragma unroll
            for (int kk = 0; kk < 16; kk++) {
                float a[8];
                *(float4*)&a[0] = *(const float4*)&Ws[cur][kk][ty * 8];
                *(float4*)&a[4] = *(const float4*)&Ws[cur][kk][ty * 8 + 4];
                float4 x0 = *(const float4*)&Xs[cur][kk][tx * 4];
                f2 b2[2] = { pk(x0.x, x0.y), pk(x0.z, x0.w) };
                #pragma unroll
                for (int i = 0; i < 8; i++) {
                    f2 a2 = pk(a[i], a[i]);
                    acc2[i][0] = fma2(a2, b2[0], acc2[i][0]);
                    acc2[i][1] = fma2(a2, b2[1], acc2[i][1]);
                }
            }
            cpa_wait0();
            __syncthreads();
            cur = nxt;
        }

        #pragma unroll
        for (int i = 0; i < 8; i++) {
            int c = DTC + ty * 8 + i;
            float o[4];
            up2(acc2[i][0], o[0], o[1]);
            up2(acc2[i][1], o[2], o[3]);
            *(float4*)&g_scratch[c * NROWS + rBase + tx * 4] = *(float4*)&o[0];
        }
    }
}

// ---------------- kernel 2: SSM — R8 winner (unchanged) ----------------
#define SHS 36
__global__ __launch_bounds__(128, 4) void ssm_kernel(const float* __restrict__ conv_w,
                                                     const float* __restrict__ ralpha,
                                                     const float* __restrict__ rbeta,
                                                     const float* __restrict__ Dparam,
                                                     const float* __restrict__ A_log,
                                                     float* __restrict__ y) {
    __shared__ float shR[2][32][SHS];
    __shared__ float shI[2][32][SHS];

    int d   = blockIdx.x;
    int b   = blockIdx.y;
    int t   = threadIdx.x;
    int R0  = (t >> 3) * 2;
    int lane8 = t & 7;
    int pcb = lane8 * 4;
    int row0 = b * NTOK;
    int n0 = R0 * 32 + pcb;
    int n1 = n0 + 32;

    int rm = (R0 > 0)      ? R0 - 1 : 0;
    int rp = (R0 + 2 < 32) ? R0 + 2 : 31;

    f2 w2[9];
    #pragma unroll
    for (int i = 0; i < 9; i++) { float wv = conv_w[d * 9 + i]; w2[i] = pk(wv, wv); }
    float alpha = ralpha[d];
    float beta  = rbeta[d];
    float Dp    = Dparam[d];
    const f2 HALF2 = pk(0.5f, 0.5f);

    float xv[8], yacc[8];
    f2 ds2[8], dd2[8];
    {
        float4 a = *(const float4*)&g_xT[d * NROWS + row0 + n0];
        float4 c = *(const float4*)&g_xT[d * NROWS + row0 + n1];
        xv[0]=a.x; xv[1]=a.y; xv[2]=a.z; xv[3]=a.w;
        xv[4]=c.x; xv[5]=c.y; xv[6]=c.z; xv[7]=c.w;
        a = *(const float4*)&g_scratch[d * NROWS + row0 + n0];
        c = *(const float4*)&g_scratch[d * NROWS + row0 + n1];
        ds2[0]=pk(a.x,a.x); ds2[1]=pk(a.y,a.y); ds2[2]=pk(a.z,a.z); ds2[3]=pk(a.w,a.w);
        ds2[4]=pk(c.x,c.x); ds2[5]=pk(c.y,c.y); ds2[6]=pk(c.z,c.z); ds2[7]=pk(c.w,c.w);
        a = *(const float4*)&g_scratch[(384 + d) * NROWS + row0 + n0];
        c = *(const float4*)&g_scratch[(384 + d) * NROWS + row0 + n1];
        dd2[0]=pk(a.x,a.x); dd2[1]=pk(a.y,a.y); dd2[2]=pk(a.z,a.z); dd2[3]=pk(a.w,a.w);
        dd2[4]=pk(c.x,c.x); dd2[5]=pk(c.y,c.y); dd2[6]=pk(c.z,c.z); dd2[7]=pk(c.w,c.w);
    }
    #pragma unroll
    for (int j = 0; j < 8; j++) yacc[j] = xv[j] * Dp;

    int buf = 0;
    for (int s = 0; s < SST; s++) {
        float A = -softplusf(A_log[d * SST + s]);
        f2 A2 = pk(A, A);
        f2 u2[8], hc[8];
        {
            float4 a = *(const float4*)&g_scratch[(768 + s) * NROWS + row0 + n0];
            float4 c = *(const float4*)&g_scratch[(768 + s) * NROWS + row0 + n1];
            u2[0] = pk(xv[0]*a.x, 0.f); u2[1] = pk(xv[1]*a.y, 0.f);
            u2[2] = pk(xv[2]*a.z, 0.f); u2[3] = pk(xv[3]*a.w, 0.f);
            u2[4] = pk(xv[4]*c.x, 0.f); u2[5] = pk(xv[5]*c.y, 0.f);
            u2[6] = pk(xv[6]*c.z, 0.f); u2[7] = pk(xv[7]*c.w, 0.f);
        }
        #pragma unroll
        for (int j = 0; j < 8; j++) hc[j] = u2[j];

        #pragma unroll
        for (int step = 0; step < 2; step++) {
            {
                float a0,b0,a1,b1,a2,b2,a3,b3;
                up2(hc[0],a0,b0); up2(hc[1],a1,b1); up2(hc[2],a2,b2); up2(hc[3],a3,b3);
                *(float4*)&shR[buf][R0][pcb] = make_float4(a0,a1,a2,a3);
                *(float4*)&shI[buf][R0][pcb] = make_float4(b0,b1,b2,b3);
                up2(hc[4],a0,b0); up2(hc[5],a1,b1); up2(hc[6],a2,b2); up2(hc[7],a3,b3);
                *(float4*)&shR[buf][R0+1][pcb] = make_float4(a0,a1,a2,a3);
                *(float4*)&shI[buf][R0+1][pcb] = make_float4(b0,b1,b2,b3);
            }
            __syncthreads();

            int cl = (pcb > 0)  ? pcb - 1 : 0;
            int cr = (pcb < 28) ? pcb + 4 : 31;
            float4 tR4 = *(const float4*)&shR[buf][rm][pcb];
            float4 tI4 = *(const float4*)&shI[buf][rm][pcb];
            float  tRl = shR[buf][rm][cl], tIl = shI[buf][rm][cl];
            float  tRr = shR[buf][rm][cr], tIr = shI[buf][rm][cr];
            float4 bR4 = *(const float4*)&shR[buf][rp][pcb];
            float4 bI4 = *(const float4*)&shI[buf][rp][pcb];
            float  bRl = shR[buf][rp][cl], bIl = shI[buf][rp][cl];
            float  bRr = shR[buf][rp][cr], bIr = shI[buf][rp][cr];

            float h0r,h0i,h3r,h3i,h4r,h4i,h7r,h7i;
            up2(hc[0],h0r,h0i); up2(hc[3],h3r,h3i);
            up2(hc[4],h4r,h4i); up2(hc[7],h7r,h7i);
            float e0lr = __shfl_up_sync(0xffffffffu,   h3r, 1);
            float e0li = __shfl_up_sync(0xffffffffu,   h3i, 1);
            float e0rr = __shfl_down_sync(0xffffffffu, h0r, 1);
            float e0ri = __shfl_down_sync(0xffffffffu, h0i, 1);
            float e1lr = __shfl_up_sync(0xffffffffu,   h7r, 1);
            float e1li = __shfl_up_sync(0xffffffffu,   h7i, 1);
            float e1rr = __shfl_down_sync(0xffffffffu, h4r, 1);
            float e1ri = __shfl_down_sync(0xffffffffu, h4i, 1);
            if (lane8 == 0) { e0lr=h0r; e0li=h0i; e1lr=h4r; e1li=h4i; }
            if (lane8 == 7) { e0rr=h3r; e0ri=h3i; e1rr=h7r; e1ri=h7i; }

            f2 T[6]  = { pk(tRl,tIl), pk(tR4.x,tI4.x), pk(tR4.y,tI4.y),
                         pk(tR4.z,tI4.z), pk(tR4.w,tI4.w), pk(tRr,tIr) };
            f2 Bw[6] = { pk(bRl,bIl), pk(bR4.x,bI4.x), pk(bR4.y,bI4.y),
                         pk(bR4.z,bI4.z), pk(bR4.w,bI4.w), pk(bRr,bIr) };
            f2 M0[6] = { pk(e0lr,e0li), hc[0], hc[1], hc[2], hc[3], pk(e0rr,e0ri) };
            f2 M1[6] = { pk(e1lr,e1li), hc[4], hc[5], hc[6], hc[7], pk(e1rr,e1ri) };

            f2 hn[8];
            #pragma unroll
            for (int c = 0; c < 4; c++) {
                f2 lap = mul2(w2[0], T[c]);
                lap = fma2(w2[1], T[c+1], lap);
                lap = fma2(w2[2], T[c+2], lap);
                lap = fma2(w2[3], M0[c],   lap);
                lap = fma2(w2[4], M0[c+1], lap);
                lap = fma2(w2[5], M0[c+2], lap);
                lap = fma2(w2[6], M1[c],   lap);
                lap = fma2(w2[7], M1[c+1], lap);
                lap = fma2(w2[8], M1[c+2], lap);
                {
                    float hrj, hij; up2(hc[c], hrj, hij);
                    float h2 = fmaf(hrj, hrj, hij * hij);
                    float rs = fmaf(-beta, h2, alpha);
                    f2 f1 = mul2(ds2[c], fma2(A2, hc[c], u2[c]));
                    float lr, li; up2(lap, lr, li);
                    f2 sum = fma2(dd2[c], pk(-li, lr), f1);
                    sum = fma2(hc[c], pk(rs, rs), sum);
                    hn[c] = fma2(HALF2, sum, hc[c]);
                }
                f2 lap2 = mul2(w2[0], M0[c]);
                lap2 = fma2(w2[1], M0[c+1], lap2);
                lap2 = fma2(w2[2], M0[c+2], lap2);
                lap2 = fma2(w2[3], M1[c],   lap2);
                lap2 = fma2(w2[4], M1[c+1], lap2);
                lap2 = fma2(w2[5], M1[c+2], lap2);
                lap2 = fma2(w2[6], Bw[c],   lap2);
                lap2 = fma2(w2[7], Bw[c+1], lap2);
                lap2 = fma2(w2[8], Bw[c+2], lap2);
                {
                    int j = 4 + c;
                    float hrj, hij; up2(hc[j], hrj, hij);
                    float h2 = fmaf(hrj, hrj, hij * hij);
                    float rs = fmaf(-beta, h2, alpha);
                    f2 f1 = mul2(ds2[j], fma2(A2, hc[j], u2[j]));
                    float lr, li; up2(lap2, lr, li);
                    f2 sum = fma2(dd2[j], pk(-li, lr), f1);
                    sum = fma2(hc[j], pk(rs, rs), sum);
                    hn[j] = fma2(HALF2, sum, hc[j]);
                }
            }
            #pragma unroll
            for (int j = 0; j < 8; j++) hc[j] = hn[j];
            buf ^= 1;
        }

        {
            float4 c0 = *(const float4*)&g_scratch[(784 + s) * NROWS + row0 + n0];
            float4 c1 = *(const float4*)&g_scratch[(784 + s) * NROWS + row0 + n1];
            float4 i0 = *(const float4*)&g_scratch[(800 + s) * NROWS + row0 + n0];
            float4 i1 = *(const float4*)&g_scratch[(800 + s) * NROWS + row0 + n1];
            float hr, hi;
            up2(hc[0], hr, hi); yacc[0] = fmaf(hr, c0.x, fmaf(hi, i0.x, yacc[0]));
            up2(hc[1], hr, hi); yacc[1] = fmaf(hr, c0.y, fmaf(hi, i0.y, yacc[1]));
            up2(hc[2], hr, hi); yacc[2] = fmaf(hr, c0.z, fmaf(hi, i0.z, yacc[2]));
            up2(hc[3], hr, hi); yacc[3] = fmaf(hr, c0.w, fmaf(hi, i0.w, yacc[3]));
            up2(hc[4], hr, hi); yacc[4] = fmaf(hr, c1.x, fmaf(hi, i1.x, yacc[4]));
            up2(hc[5], hr, hi); yacc[5] = fmaf(hr, c1.y, fmaf(hi, i1.y, yacc[5]));
            up2(hc[6], hr, hi); yacc[6] = fmaf(hr, c1.z, fmaf(hi, i1.z, yacc[6]));
            up2(hc[7], hr, hi); yacc[7] = fmaf(hr, c1.w, fmaf(hi, i1.w, yacc[7]));
        }
    }

    #pragma unroll
    for (int j = 0; j < 4; j++) {
        y[(row0 + n0 + j) * DIN + d] = yacc[j];
        y[(row0 + n1 + j) * DIN + d] = yacc[4 + j];
    }
}

// ---------------- launch ----------------
extern "C" void kernel_launch(void* const* d_in, const int* in_sizes, int n_in,
                              void* d_out, int out_size) {
    const float* x      = (const float*)d_in[0];
    const float* dtsW   = (const float*)d_in[1];
    const float* dtsb   = (const float*)d_in[2];
    const float* dtdW   = (const float*)d_in[3];
    const float* dtdb   = (const float*)d_in[4];
    const float* BW     = (const float*)d_in[5];
    const float* CrW    = (const float*)d_in[6];
    const float* CiW    = (const float*)d_in[7];
    const float* Dparam = (const float*)d_in[8];
    const float* A_log  = (const float*)d_in[9];
    const float* conv_w = (const float*)d_in[10];
    const float* ralpha = (const float*)d_in[11];
    const float* rbeta  = (const float*)d_in[12];
    float* y = (float*)d_out;

    prep_kernel<<<PREP_PACK + PREP_CONV + PREP_TRANS, 256>>>(
        x, dtsW, dtsb, dtdW, dtdb, BW, CrW, CiW);
    gemm_fused<<<dim3(14, NROWS / 128), 128>>>();
    ssm_kernel<<<dim3(DIN, BSZ), 128>>>(conv_w, ralpha, rbeta, Dparam, A_log, y);
}